// round 7
// baseline (speedup 1.0000x reference)
#include <cuda_runtime.h>
#include <cuda_bf16.h>
#include <math.h>
#include <stdint.h>

// ---------------- problem constants ----------------
#define BB 8
#define TT 2048
#define VDIM 1024
#define ADIM 768
#define DM 256
#define HID 1024
#define MROWS (BB*TT)     /* 16384 */
#define XDIM (3*DM)       /* 768 */

// ---------------- device scratch ----------------
__device__ __align__(16) float g_v[MROWS*DM];
__device__ __align__(16) float g_a[MROWS*DM];
__device__ __align__(16) float g_actx[MROWS*DM];
__device__ __align__(16) float g_h[MROWS*HID];
__device__ float g_rnv[MROWS];
__device__ float g_rna[MROWS];
// bf16 split operands
__device__ __align__(16) __nv_bfloat16 g_vh[MROWS*VDIM];
__device__ __align__(16) __nv_bfloat16 g_vl[MROWS*VDIM];
__device__ __align__(16) __nv_bfloat16 g_auh[MROWS*ADIM];
__device__ __align__(16) __nv_bfloat16 g_aul[MROWS*ADIM];
__device__ __align__(16) __nv_bfloat16 g_xh[MROWS*XDIM];
__device__ __align__(16) __nv_bfloat16 g_xl[MROWS*XDIM];
// transposed split weights [N,K]
__device__ __align__(16) __nv_bfloat16 g_wvh[DM*VDIM],  g_wvl[DM*VDIM];
__device__ __align__(16) __nv_bfloat16 g_wah[DM*ADIM],  g_wal[DM*ADIM];
__device__ __align__(16) __nv_bfloat16 g_w1h[HID*XDIM], g_w1l[HID*XDIM];

// ---------------- helpers ----------------
__device__ __forceinline__ float warp_sum(float v) {
#pragma unroll
    for (int o = 16; o > 0; o >>= 1) v += __shfl_xor_sync(0xffffffffu, v, o);
    return v;
}
__device__ __forceinline__ float gelu_exact(float x) {
    return 0.5f * x * (1.0f + erff(x * 0.70710678118654752f));
}
__device__ __forceinline__ void split1(float x, __nv_bfloat16& h, __nv_bfloat16& l) {
    h = __float2bfloat16(x);
    l = __float2bfloat16(x - __bfloat162float(h));
}
__device__ __forceinline__ void cp_async16(uint32_t dst, const void* src) {
    asm volatile("cp.async.cg.shared.global [%0], [%1], 16;" :: "r"(dst), "l"(src));
}
__device__ __forceinline__ void cp_commit() {
    asm volatile("cp.async.commit_group;" ::: "memory");
}
template<int N> __device__ __forceinline__ void cp_wait() {
    asm volatile("cp.async.wait_group %0;" :: "n"(N) : "memory");
}
__device__ __forceinline__ uint32_t smem_u32(const void* p) {
    uint32_t a;
    asm("{ .reg .u64 t; cvta.to.shared.u64 t, %1; cvt.u32.u64 %0, t; }" : "=r"(a) : "l"(p));
    return a;
}
// mma.sync m16n8k16 bf16 (row.col), fp32 accum
__device__ __forceinline__ void mma_bf16(float* c, const uint32_t* a, const uint32_t* b) {
    asm volatile(
        "mma.sync.aligned.m16n8k16.row.col.f32.bf16.bf16.f32 "
        "{%0,%1,%2,%3}, {%4,%5,%6,%7}, {%8,%9}, {%0,%1,%2,%3};"
        : "+f"(c[0]), "+f"(c[1]), "+f"(c[2]), "+f"(c[3])
        : "r"(a[0]), "r"(a[1]), "r"(a[2]), "r"(a[3]), "r"(b[0]), "r"(b[1]));
}
__device__ __forceinline__ void ldsm_x4(uint32_t* r, uint32_t addr) {
    asm volatile("ldmatrix.sync.aligned.m8n8.x4.shared.b16 {%0,%1,%2,%3}, [%4];"
        : "=r"(r[0]), "=r"(r[1]), "=r"(r[2]), "=r"(r[3]) : "r"(addr));
}

// ---------------- mma.sync split-bf16 GEMM (ldmatrix fragment loads) ----------------
// C[M,N] = A[M,K] @ B^T, B stored [N,K] K-major. A=Ah+Al, B=Bh+Bl.
// Accumulate AhBh + AhBl + AlBh in fp32.
// Block tile 128x128, BK=32, 8 warps (4 M x 2 N), warp tile 32x64.
#define SROW 40                        /* smem row stride in bf16 (80 bytes) */
#define SROWB (SROW*2)                 /* 80 bytes */
#define OP_BYTES (128*SROWB)           /* 10240 B per operand */
#define STAGE_BYTES (4*OP_BYTES)       /* 40960 B */
#define SMEM_TOTAL_GEMM (2*STAGE_BYTES)/* 81920 B */

template<bool GELU>
__global__ void __launch_bounds__(256, 1) tc_gemm(
    const __nv_bfloat16* __restrict__ Ah, const __nv_bfloat16* __restrict__ Al,
    const __nv_bfloat16* __restrict__ Bh, const __nv_bfloat16* __restrict__ Bl,
    const float* __restrict__ bias, float* __restrict__ C, int K, int N)
{
    extern __shared__ __nv_bfloat16 smem[];
    uint32_t sbase = smem_u32(smem);
    const int tid    = threadIdx.x;
    const int wid    = tid >> 5;
    const int lane   = tid & 31;
    const int warp_m = wid >> 1;          // 0..3
    const int warp_n = wid & 1;           // 0..1
    const int lr     = lane >> 2;         // 0..7
    const int lc     = lane & 3;          // 0..3
    const int lr8    = lane & 7;          // 0..7
    const int lg     = lane >> 3;         // 0..3 (ldmatrix group)
    const int row0   = blockIdx.y * 128;
    const int col0   = blockIdx.x * 128;

    const __nv_bfloat16* Ahp = Ah + (size_t)row0 * K;
    const __nv_bfloat16* Alp = Al + (size_t)row0 * K;
    const __nv_bfloat16* Bhp = Bh + (size_t)col0 * K;
    const __nv_bfloat16* Blp = Bl + (size_t)col0 * K;

    const int nk = K >> 5;   // BK=32 iterations

    // ldmatrix per-thread base offsets (bytes, within one operand tile)
    // A m16-tile im: mat order (r,c)=(+0,0),(+8,0),(+0,8),(+8,8)
    uint32_t aoff[2], boff[4];
#pragma unroll
    for (int im = 0; im < 2; im++)
        aoff[im] = (uint32_t)((warp_m*32 + im*16 + (lg & 1)*8 + lr8) * SROWB + ((lg >> 1)*8) * 2);
    // B n16-pair ip: mat order (n,k)=(+0,0),(+0,8),(+8,0),(+8,8)
#pragma unroll
    for (int ip = 0; ip < 4; ip++)
        boff[ip] = (uint32_t)((warp_n*64 + ip*16 + (lg >> 1)*8 + lr8) * SROWB + ((lg & 1)*8) * 2);

    // cp.async stage loader: 128 rows x 32 cols bf16 per operand, 4x16B per row
    auto load_stage = [&](int kt, int stg) {
        uint32_t sb = sbase + stg * STAGE_BYTES;
        int koff = kt * 32;
#pragma unroll
        for (int i = 0; i < 2; i++) {
            int id = tid + i * 256;           // 0..511
            int r  = id >> 2;                 // 0..127
            int c  = id & 3;                  // 0..3 (16B chunks)
            uint32_t soff = (uint32_t)(r * SROWB + c * 16);
            size_t   goff = (size_t)r * K + koff + c * 8;
            cp_async16(sb +              soff, Ahp + goff);
            cp_async16(sb + OP_BYTES   + soff, Alp + goff);
            cp_async16(sb + OP_BYTES*2 + soff, Bhp + goff);
            cp_async16(sb + OP_BYTES*3 + soff, Blp + goff);
        }
        cp_commit();
    };

    float acc[2][8][4];
#pragma unroll
    for (int im = 0; im < 2; im++)
#pragma unroll
        for (int in = 0; in < 8; in++)
#pragma unroll
            for (int j = 0; j < 4; j++) acc[im][in][j] = 0.f;

    load_stage(0, 0);
    for (int k = 0; k < nk; k++) {
        if (k + 1 < nk) { load_stage(k + 1, (k + 1) & 1); cp_wait<1>(); }
        else            { cp_wait<0>(); }
        __syncthreads();

        uint32_t sb  = sbase + (uint32_t)(k & 1) * STAGE_BYTES;
        uint32_t sAh = sb;
        uint32_t sAl = sb + OP_BYTES;
        uint32_t sBh = sb + OP_BYTES*2;
        uint32_t sBl = sb + OP_BYTES*3;

#pragma unroll
        for (int kk = 0; kk < 2; kk++) {
            uint32_t kb = (uint32_t)(kk * 32);   // 16 bf16 = 32 bytes
            uint32_t aH[2][4], aL[2][4], bH[8][2], bL[8][2];
#pragma unroll
            for (int im = 0; im < 2; im++) {
                ldsm_x4(aH[im], sAh + aoff[im] + kb);
                ldsm_x4(aL[im], sAl + aoff[im] + kb);
            }
#pragma unroll
            for (int ip = 0; ip < 4; ip++) {
                uint32_t t[4];
                ldsm_x4(t, sBh + boff[ip] + kb);
                bH[2*ip][0] = t[0]; bH[2*ip][1] = t[1];
                bH[2*ip+1][0] = t[2]; bH[2*ip+1][1] = t[3];
                ldsm_x4(t, sBl + boff[ip] + kb);
                bL[2*ip][0] = t[0]; bL[2*ip][1] = t[1];
                bL[2*ip+1][0] = t[2]; bL[2*ip+1][1] = t[3];
            }
            // 3-term split MMA
#pragma unroll
            for (int im = 0; im < 2; im++)
#pragma unroll
                for (int in = 0; in < 8; in++) {
                    mma_bf16(acc[im][in], aH[im], bH[in]);
                    mma_bf16(acc[im][in], aH[im], bL[in]);
                    mma_bf16(acc[im][in], aL[im], bH[in]);
                }
        }
        __syncthreads();
    }

    // epilogue: + bias, optional gelu, st.64 per fragment half
#pragma unroll
    for (int im = 0; im < 2; im++) {
        int r0 = row0 + warp_m * 32 + im * 16 + lr;
#pragma unroll
        for (int in = 0; in < 8; in++) {
            int c = col0 + warp_n * 64 + in * 8 + lc * 2;
            float b0 = bias[c], b1 = bias[c + 1];
            float2 v0, v1;
            v0.x = acc[im][in][0] + b0; v0.y = acc[im][in][1] + b1;
            v1.x = acc[im][in][2] + b0; v1.y = acc[im][in][3] + b1;
            if (GELU) {
                v0.x = gelu_exact(v0.x); v0.y = gelu_exact(v0.y);
                v1.x = gelu_exact(v1.x); v1.y = gelu_exact(v1.y);
            }
            *(float2*)&C[(size_t)(r0    ) * N + c] = v0;
            *(float2*)&C[(size_t)(r0 + 8) * N + c] = v1;
        }
    }
}

// ---------------- pre-pass: split fp32 -> bf16 hi/lo ----------------
__global__ void __launch_bounds__(256) split_kernel(
    const float* __restrict__ X, __nv_bfloat16* __restrict__ H,
    __nv_bfloat16* __restrict__ L, int n4)
{
    int i = blockIdx.x * 256 + threadIdx.x;
    if (i >= n4) return;
    float4 x = ((const float4*)X)[i];
    __nv_bfloat16 h[4], l[4];
    split1(x.x, h[0], l[0]); split1(x.y, h[1], l[1]);
    split1(x.z, h[2], l[2]); split1(x.w, h[3], l[3]);
    ((uint2*)H)[i] = *(uint2*)h;
    ((uint2*)L)[i] = *(uint2*)l;
}

// ---------------- pre-pass: transpose + split weights [K,N] -> [N,K] ----------------
__global__ void __launch_bounds__(256) wsplit_kernel(
    const float* __restrict__ W, __nv_bfloat16* __restrict__ Ht,
    __nv_bfloat16* __restrict__ Lt, int K, int N)
{
    int i = blockIdx.x * 256 + threadIdx.x;
    if (i >= K * N) return;
    int k = i / N, n = i % N;
    __nv_bfloat16 h, l;
    split1(W[i], h, l);
    Ht[(size_t)n * K + k] = h;
    Lt[(size_t)n * K + k] = l;
}

// ---------------- LayerNorm in place + optional 1/||.|| output ----------------
__global__ void __launch_bounds__(256) ln_kernel(float* __restrict__ X, float* __restrict__ rn)
{
    int row  = blockIdx.x * 8 + (threadIdx.x >> 5);
    int lane = threadIdx.x & 31;
    float* p = X + (size_t)row * DM + lane * 8;
    float4 u0 = *(const float4*)p;
    float4 u1 = *(const float4*)(p + 4);
    float s = u0.x + u0.y + u0.z + u0.w + u1.x + u1.y + u1.z + u1.w;
    s = warp_sum(s);
    float mu = s * (1.0f / DM);
    float d[8] = {u0.x-mu, u0.y-mu, u0.z-mu, u0.w-mu, u1.x-mu, u1.y-mu, u1.z-mu, u1.w-mu};
    float q = 0.f;
#pragma unroll
    for (int i = 0; i < 8; i++) q += d[i] * d[i];
    q = warp_sum(q);
    float inv = 1.0f / sqrtf(q * (1.0f / DM) + 1e-5f);
    float o[8];
#pragma unroll
    for (int i = 0; i < 8; i++) o[i] = d[i] * inv;
    *(float4*)p       = *(float4*)&o[0];
    *(float4*)(p + 4) = *(float4*)&o[4];
    if (rn && lane == 0) {
        // ||o||^2 = q * inv^2 (analytic)
        float nrm = sqrtf(q) * inv;
        rn[row] = 1.0f / fmaxf(nrm, 1e-8f);
    }
}

// ---------------- fractional shift + causal window average ----------------
__global__ void __launch_bounds__(256) shiftbox_kernel(
    const float* __restrict__ A, float* __restrict__ Out,
    const float* __restrict__ theta)
{
    int gid = blockIdx.x * 256 + threadIdx.x;
    int row = gid >> 6;
    int d4  = gid & 63;
    int b = row / TT, t = row % TT;

    float th    = fminf(fmaxf(theta[0], -12.0f), 12.0f);
    float delta = 2.0f + 4.0f / (1.0f + expf(-th));
    float dl    = fminf(fmaxf(delta, 0.0f), (float)(TT - 1));
    float nf    = floorf(dl);
    float alpha = dl - nf;
    int   ni    = (int)nf;

    float center = fminf(fmaxf((float)t + delta, 0.0f), (float)t);
    int lo = max(0, (int)ceilf(center - 5.0f));
    int hi = min(t, (int)floorf(center + 5.0f));

    const float4* Av = (const float4*)A;
    float4 acc = make_float4(0.f, 0.f, 0.f, 0.f);
    float w0 = 1.0f - alpha, w1 = alpha;
    for (int tau = lo; tau <= hi; tau++) {
        int i0 = min(max(tau - ni, 0), TT - 1);
        int i1 = min(i0 + 1, TT - 1);
        float4 x0 = Av[(size_t)(b * TT + i0) * 64 + d4];
        float4 x1 = Av[(size_t)(b * TT + i1) * 64 + d4];
        acc.x += w0 * x0.x + w1 * x1.x;
        acc.y += w0 * x0.y + w1 * x1.y;
        acc.z += w0 * x0.z + w1 * x1.z;
        acc.w += w0 * x0.w + w1 * x1.w;
    }
    float scale = 1.0f / fmaxf((float)(hi - lo + 1), 1e-8f);
    acc.x *= scale; acc.y *= scale; acc.z *= scale; acc.w *= scale;
    ((float4*)Out)[(size_t)row * 64 + d4] = acc;
}

// ---------------- reciprocal L2 norm per row ----------------
__global__ void __launch_bounds__(256) rnorm_kernel(
    const float* __restrict__ X, float* __restrict__ rn)
{
    int row  = blockIdx.x * 8 + (threadIdx.x >> 5);
    int lane = threadIdx.x & 31;
    const float* p = X + (size_t)row * DM + lane * 8;
    float4 u0 = *(const float4*)p;
    float4 u1 = *(const float4*)(p + 4);
    float q = u0.x*u0.x + u0.y*u0.y + u0.z*u0.z + u0.w*u0.w
            + u1.x*u1.x + u1.y*u1.y + u1.z*u1.z + u1.w*u1.w;
    q = warp_sum(q);
    if (lane == 0) rn[row] = 1.0f / fmaxf(sqrtf(q), 1e-8f);
}

// ---------------- build x = [an, vn, an*vn] directly as bf16 hi/lo ----------------
__global__ void __launch_bounds__(256) buildx_kernel(
    const float* __restrict__ Actx, const float* __restrict__ V,
    const float* __restrict__ rna, const float* __restrict__ rnv,
    __nv_bfloat16* __restrict__ XH, __nv_bfloat16* __restrict__ XL)
{
    int gid = blockIdx.x * 256 + threadIdx.x;
    int row = gid >> 6;
    int d4  = gid & 63;
    float ra = rna[row], rv = rnv[row];
    float4 a = ((const float4*)Actx)[(size_t)row * 64 + d4];
    float4 v = ((const float4*)V)[(size_t)row * 64 + d4];
    float an[4] = {a.x*ra, a.y*ra, a.z*ra, a.w*ra};
    float vn[4] = {v.x*rv, v.y*rv, v.z*rv, v.w*rv};
    float pr[4] = {an[0]*vn[0], an[1]*vn[1], an[2]*vn[2], an[3]*vn[3]};

    size_t base = (size_t)row * XDIM;
    __nv_bfloat16 h[4], l[4];
#pragma unroll
    for (int i = 0; i < 4; i++) split1(an[i], h[i], l[i]);
    *(uint2*)&XH[base + 4*d4] = *(uint2*)h;
    *(uint2*)&XL[base + 4*d4] = *(uint2*)l;
#pragma unroll
    for (int i = 0; i < 4; i++) split1(vn[i], h[i], l[i]);
    *(uint2*)&XH[base + DM + 4*d4] = *(uint2*)h;
    *(uint2*)&XL[base + DM + 4*d4] = *(uint2*)l;
#pragma unroll
    for (int i = 0; i < 4; i++) split1(pr[i], h[i], l[i]);
    *(uint2*)&XH[base + 2*DM + 4*d4] = *(uint2*)h;
    *(uint2*)&XL[base + 2*DM + 4*d4] = *(uint2*)l;
}

// ---------------- final: logit = h@W2+b2, gate, blend (warp per row) ----------------
__global__ void __launch_bounds__(256) final_kernel(
    const float* __restrict__ H, const float* __restrict__ Actx,
    const float* __restrict__ V, const float* __restrict__ W2,
    const float* __restrict__ b2, float* __restrict__ Out)
{
    int row  = blockIdx.x * 8 + (threadIdx.x >> 5);
    int lane = threadIdx.x & 31;
    const float* hr = H + (size_t)row * HID;
    float s = 0.f;
#pragma unroll
    for (int i = 0; i < 32; i++) {
        int k = i * 32 + lane;
        s = fmaf(hr[k], W2[k], s);
    }
    s = warp_sum(s);
    float logit = fminf(fmaxf(s + b2[0], -12.0f), 12.0f);
    float g = 1.0f / (1.0f + expf(-logit));
    g = fminf(fmaxf(g, 0.05f), 0.95f);
    float om = 1.0f - g;

    const float4* av = (const float4*)(Actx + (size_t)row * DM);
    const float4* vv = (const float4*)(V    + (size_t)row * DM);
    float4*       ov = (float4*)(Out + (size_t)row * DM);
#pragma unroll
    for (int j = 0; j < 2; j++) {
        int d4 = lane * 2 + j;
        float4 a = av[d4], v = vv[d4];
        ov[d4] = make_float4(g*a.x + om*v.x, g*a.y + om*v.y,
                             g*a.z + om*v.z, g*a.w + om*v.w);
    }
}

// ---------------- launch ----------------
extern "C" void kernel_launch(void* const* d_in, const int* in_sizes, int n_in,
                              void* d_out, int out_size)
{
    const float* video = (const float*)d_in[0];
    const float* audio = (const float*)d_in[1];
    const float* Wv    = (const float*)d_in[2];
    const float* bv    = (const float*)d_in[3];
    const float* Wa    = (const float*)d_in[4];
    const float* ba    = (const float*)d_in[5];
    const float* theta = (const float*)d_in[6];
    const float* W1    = (const float*)d_in[7];
    const float* b1    = (const float*)d_in[8];
    const float* W2    = (const float*)d_in[9];
    const float* b2    = (const float*)d_in[10];
    float* out = (float*)d_out;

    float *pv, *pa, *pactx, *ph, *prnv, *prna;
    __nv_bfloat16 *pvh, *pvl, *pauh, *paul, *pxh, *pxl;
    __nv_bfloat16 *pwvh, *pwvl, *pwah, *pwal, *pw1h, *pw1l;
    cudaGetSymbolAddress((void**)&pv,    g_v);
    cudaGetSymbolAddress((void**)&pa,    g_a);
    cudaGetSymbolAddress((void**)&pactx, g_actx);
    cudaGetSymbolAddress((void**)&ph,    g_h);
    cudaGetSymbolAddress((void**)&prnv,  g_rnv);
    cudaGetSymbolAddress((void**)&prna,  g_rna);
    cudaGetSymbolAddress((void**)&pvh,   g_vh);
    cudaGetSymbolAddress((void**)&pvl,   g_vl);
    cudaGetSymbolAddress((void**)&pauh,  g_auh);
    cudaGetSymbolAddress((void**)&paul,  g_aul);
    cudaGetSymbolAddress((void**)&pxh,   g_xh);
    cudaGetSymbolAddress((void**)&pxl,   g_xl);
    cudaGetSymbolAddress((void**)&pwvh,  g_wvh);
    cudaGetSymbolAddress((void**)&pwvl,  g_wvl);
    cudaGetSymbolAddress((void**)&pwah,  g_wah);
    cudaGetSymbolAddress((void**)&pwal,  g_wal);
    cudaGetSymbolAddress((void**)&pw1h,  g_w1h);
    cudaGetSymbolAddress((void**)&pw1l,  g_w1l);

    cudaFuncSetAttribute(tc_gemm<false>, cudaFuncAttributeMaxDynamicSharedMemorySize, SMEM_TOTAL_GEMM);
    cudaFuncSetAttribute(tc_gemm<true>,  cudaFuncAttributeMaxDynamicSharedMemorySize, SMEM_TOTAL_GEMM);

    // pre-pass splits
    split_kernel<<<(MROWS*VDIM/4 + 255)/256, 256>>>(video, pvh, pvl, MROWS*VDIM/4);
    split_kernel<<<(MROWS*ADIM/4 + 255)/256, 256>>>(audio, pauh, paul, MROWS*ADIM/4);
    wsplit_kernel<<<(VDIM*DM + 255)/256, 256>>>(Wv, pwvh, pwvl, VDIM, DM);
    wsplit_kernel<<<(ADIM*DM + 255)/256, 256>>>(Wa, pwah, pwal, ADIM, DM);
    wsplit_kernel<<<(XDIM*HID + 255)/256, 256>>>(W1, pw1h, pw1l, XDIM, HID);

    // projections (tensor-core mma.sync)
    tc_gemm<false><<<dim3(DM/128, MROWS/128), 256, SMEM_TOTAL_GEMM>>>(
        pvh, pvl, pwvh, pwvl, bv, pv, VDIM, DM);
    tc_gemm<false><<<dim3(DM/128, MROWS/128), 256, SMEM_TOTAL_GEMM>>>(
        pauh, paul, pwah, pwal, ba, pa, ADIM, DM);

    // layernorm in place (+ fused 1/||v|| for video)
    ln_kernel<<<MROWS/8, 256>>>(pv, prnv);
    ln_kernel<<<MROWS/8, 256>>>(pa, (float*)nullptr);
    // fractional shift + causal box filter
    shiftbox_kernel<<<(MROWS*64)/256, 256>>>(pa, pactx, theta);
    // l2 norm of a_ctx
    rnorm_kernel<<<MROWS/8, 256>>>(pactx, prna);
    // MLP input (split bf16)
    buildx_kernel<<<(MROWS*64)/256, 256>>>(pactx, pv, prna, prnv, pxh, pxl);
    // MLP hidden with exact gelu (tensor-core mma.sync)
    tc_gemm<true><<<dim3(HID/128, MROWS/128), 256, SMEM_TOTAL_GEMM>>>(
        pxh, pxl, pw1h, pw1l, b1, ph, XDIM, HID);
    // logits + gate + blend
    final_kernel<<<MROWS/8, 256>>>(ph, pactx, pv, W2, b2, out);
}

// round 8
// speedup vs baseline: 1.0258x; 1.0258x over previous
#include <cuda_runtime.h>
#include <cuda_bf16.h>
#include <math.h>
#include <stdint.h>

// ---------------- problem constants ----------------
#define BB 8
#define TT 2048
#define VDIM 1024
#define ADIM 768
#define DM 256
#define HID 1024
#define MROWS (BB*TT)     /* 16384 */
#define XDIM (3*DM)       /* 768 */

// ---------------- device scratch ----------------
__device__ __align__(16) float g_v[MROWS*DM];
__device__ __align__(16) float g_a[MROWS*DM];
__device__ __align__(16) float g_actx[MROWS*DM];
__device__ __align__(16) float g_h[MROWS*HID];
__device__ float g_rnv[MROWS];
__device__ float g_rna[MROWS];
// bf16 split operands
__device__ __align__(16) __nv_bfloat16 g_vh[MROWS*VDIM];
__device__ __align__(16) __nv_bfloat16 g_vl[MROWS*VDIM];
__device__ __align__(16) __nv_bfloat16 g_auh[MROWS*ADIM];
__device__ __align__(16) __nv_bfloat16 g_aul[MROWS*ADIM];
__device__ __align__(16) __nv_bfloat16 g_xh[MROWS*XDIM];
__device__ __align__(16) __nv_bfloat16 g_xl[MROWS*XDIM];
// transposed split weights [N,K]
__device__ __align__(16) __nv_bfloat16 g_wvh[DM*VDIM],  g_wvl[DM*VDIM];
__device__ __align__(16) __nv_bfloat16 g_wah[DM*ADIM],  g_wal[DM*ADIM];
__device__ __align__(16) __nv_bfloat16 g_w1h[HID*XDIM], g_w1l[HID*XDIM];

// ---------------- helpers ----------------
__device__ __forceinline__ float warp_sum(float v) {
#pragma unroll
    for (int o = 16; o > 0; o >>= 1) v += __shfl_xor_sync(0xffffffffu, v, o);
    return v;
}
__device__ __forceinline__ float gelu_exact(float x) {
    return 0.5f * x * (1.0f + erff(x * 0.70710678118654752f));
}
__device__ __forceinline__ void split1(float x, __nv_bfloat16& h, __nv_bfloat16& l) {
    h = __float2bfloat16(x);
    l = __float2bfloat16(x - __bfloat162float(h));
}
__device__ __forceinline__ void cp_async16(uint32_t dst, const void* src) {
    asm volatile("cp.async.cg.shared.global [%0], [%1], 16;" :: "r"(dst), "l"(src));
}
__device__ __forceinline__ void cp_commit() {
    asm volatile("cp.async.commit_group;" ::: "memory");
}
template<int N> __device__ __forceinline__ void cp_wait() {
    asm volatile("cp.async.wait_group %0;" :: "n"(N) : "memory");
}
__device__ __forceinline__ uint32_t smem_u32(const void* p) {
    uint32_t a;
    asm("{ .reg .u64 t; cvta.to.shared.u64 t, %1; cvt.u32.u64 %0, t; }" : "=r"(a) : "l"(p));
    return a;
}
// mma.sync m16n8k16 bf16 (row.col), fp32 accum
__device__ __forceinline__ void mma_bf16(float* c, const uint32_t* a, const uint32_t* b) {
    asm volatile(
        "mma.sync.aligned.m16n8k16.row.col.f32.bf16.bf16.f32 "
        "{%0,%1,%2,%3}, {%4,%5,%6,%7}, {%8,%9}, {%0,%1,%2,%3};"
        : "+f"(c[0]), "+f"(c[1]), "+f"(c[2]), "+f"(c[3])
        : "r"(a[0]), "r"(a[1]), "r"(a[2]), "r"(a[3]), "r"(b[0]), "r"(b[1]));
}
__device__ __forceinline__ void ldsm_x4(uint32_t* r, uint32_t addr) {
    asm volatile("ldmatrix.sync.aligned.m8n8.x4.shared.b16 {%0,%1,%2,%3}, [%4];"
        : "=r"(r[0]), "=r"(r[1]), "=r"(r[2]), "=r"(r[3]) : "r"(addr));
}

// ---------------- mma.sync split-bf16 GEMM (3-stage pipeline) ----------------
// C[M,N] = A[M,K] @ B^T, B stored [N,K] K-major. A=Ah+Al, B=Bh+Bl.
// Accumulate AhBh + AhBl + AlBh in fp32.
// Block tile 128x128, BK=32, 8 warps (4 M x 2 N), warp tile 32x64.
#define SROW 40                        /* smem row stride in bf16 (80 bytes) */
#define SROWB (SROW*2)                 /* 80 bytes */
#define OP_BYTES (128*SROWB)           /* 10240 B per operand */
#define STAGE_BYTES (4*OP_BYTES)       /* 40960 B */
#define NSTAGE 3
#define SMEM_TOTAL_GEMM (NSTAGE*STAGE_BYTES) /* 122880 B */

template<bool GELU>
__global__ void __launch_bounds__(256, 1) tc_gemm(
    const __nv_bfloat16* __restrict__ Ah, const __nv_bfloat16* __restrict__ Al,
    const __nv_bfloat16* __restrict__ Bh, const __nv_bfloat16* __restrict__ Bl,
    const float* __restrict__ bias, float* __restrict__ C, int K, int N)
{
    extern __shared__ __nv_bfloat16 smem[];
    uint32_t sbase = smem_u32(smem);
    const int tid    = threadIdx.x;
    const int wid    = tid >> 5;
    const int lane   = tid & 31;
    const int warp_m = wid >> 1;          // 0..3
    const int warp_n = wid & 1;           // 0..1
    const int lr     = lane >> 2;         // 0..7
    const int lc     = lane & 3;          // 0..3
    const int lr8    = lane & 7;          // 0..7
    const int lg     = lane >> 3;         // 0..3 (ldmatrix group)
    const int row0   = blockIdx.y * 128;
    const int col0   = blockIdx.x * 128;

    const __nv_bfloat16* Ahp = Ah + (size_t)row0 * K;
    const __nv_bfloat16* Alp = Al + (size_t)row0 * K;
    const __nv_bfloat16* Bhp = Bh + (size_t)col0 * K;
    const __nv_bfloat16* Blp = Bl + (size_t)col0 * K;

    const int nk = K >> 5;   // BK=32 iterations

    // ldmatrix per-thread base offsets (bytes, within one operand tile)
    uint32_t aoff[2], boff[4];
#pragma unroll
    for (int im = 0; im < 2; im++)
        aoff[im] = (uint32_t)((warp_m*32 + im*16 + (lg & 1)*8 + lr8) * SROWB + ((lg >> 1)*8) * 2);
#pragma unroll
    for (int ip = 0; ip < 4; ip++)
        boff[ip] = (uint32_t)((warp_n*64 + ip*16 + (lg >> 1)*8 + lr8) * SROWB + ((lg & 1)*8) * 2);

    // cp.async stage loader: 128 rows x 32 cols bf16 per operand, 4x16B per row
    auto load_stage = [&](int kt) {
        uint32_t sb = sbase + (uint32_t)(kt % NSTAGE) * STAGE_BYTES;
        int koff = kt * 32;
#pragma unroll
        for (int i = 0; i < 2; i++) {
            int id = tid + i * 256;           // 0..511
            int r  = id >> 2;                 // 0..127
            int c  = id & 3;                  // 0..3 (16B chunks)
            uint32_t soff = (uint32_t)(r * SROWB + c * 16);
            size_t   goff = (size_t)r * K + koff + c * 8;
            cp_async16(sb +              soff, Ahp + goff);
            cp_async16(sb + OP_BYTES   + soff, Alp + goff);
            cp_async16(sb + OP_BYTES*2 + soff, Bhp + goff);
            cp_async16(sb + OP_BYTES*3 + soff, Blp + goff);
        }
        cp_commit();
    };

    float acc[2][8][4];
#pragma unroll
    for (int im = 0; im < 2; im++)
#pragma unroll
        for (int in = 0; in < 8; in++)
#pragma unroll
            for (int j = 0; j < 4; j++) acc[im][in][j] = 0.f;

    // prologue: 2 stages in flight
    load_stage(0);
    load_stage(1);

    for (int k = 0; k < nk; k++) {
        if (k == nk - 1) cp_wait<0>();
        else             cp_wait<1>();
        __syncthreads();
        // issue next-next stage; buffer (k+2)%3 == (k-1)%3 is no longer read
        // (every warp passed this barrier => finished MMA of iter k-1)
        if (k + 2 < nk) load_stage(k + 2);

        uint32_t sb  = sbase + (uint32_t)(k % NSTAGE) * STAGE_BYTES;
        uint32_t sAh = sb;
        uint32_t sAl = sb + OP_BYTES;
        uint32_t sBh = sb + OP_BYTES*2;
        uint32_t sBl = sb + OP_BYTES*3;

#pragma unroll
        for (int kk = 0; kk < 2; kk++) {
            uint32_t kb = (uint32_t)(kk * 32);   // 16 bf16 = 32 bytes
            uint32_t aH[2][4], aL[2][4], bH[8][2], bL[8][2];
#pragma unroll
            for (int im = 0; im < 2; im++) {
                ldsm_x4(aH[im], sAh + aoff[im] + kb);
                ldsm_x4(aL[im], sAl + aoff[im] + kb);
            }
#pragma unroll
            for (int ip = 0; ip < 4; ip++) {
                uint32_t t[4];
                ldsm_x4(t, sBh + boff[ip] + kb);
                bH[2*ip][0] = t[0]; bH[2*ip][1] = t[1];
                bH[2*ip+1][0] = t[2]; bH[2*ip+1][1] = t[3];
                ldsm_x4(t, sBl + boff[ip] + kb);
                bL[2*ip][0] = t[0]; bL[2*ip][1] = t[1];
                bL[2*ip+1][0] = t[2]; bL[2*ip+1][1] = t[3];
            }
            // 3-term split MMA
#pragma unroll
            for (int im = 0; im < 2; im++)
#pragma unroll
                for (int in = 0; in < 8; in++) {
                    mma_bf16(acc[im][in], aH[im], bH[in]);
                    mma_bf16(acc[im][in], aH[im], bL[in]);
                    mma_bf16(acc[im][in], aL[im], bH[in]);
                }
        }
    }

    // epilogue: + bias, optional gelu
#pragma unroll
    for (int im = 0; im < 2; im++) {
        int r0 = row0 + warp_m * 32 + im * 16 + lr;
#pragma unroll
        for (int in = 0; in < 8; in++) {
            int c = col0 + warp_n * 64 + in * 8 + lc * 2;
            float b0 = bias[c], b1 = bias[c + 1];
            float2 v0, v1;
            v0.x = acc[im][in][0] + b0; v0.y = acc[im][in][1] + b1;
            v1.x = acc[im][in][2] + b0; v1.y = acc[im][in][3] + b1;
            if (GELU) {
                v0.x = gelu_exact(v0.x); v0.y = gelu_exact(v0.y);
                v1.x = gelu_exact(v1.x); v1.y = gelu_exact(v1.y);
            }
            *(float2*)&C[(size_t)(r0    ) * N + c] = v0;
            *(float2*)&C[(size_t)(r0 + 8) * N + c] = v1;
        }
    }
}

// ---------------- pre-pass: split fp32 -> bf16 hi/lo ----------------
__global__ void __launch_bounds__(256) split_kernel(
    const float* __restrict__ X, __nv_bfloat16* __restrict__ H,
    __nv_bfloat16* __restrict__ L, int n4)
{
    int i = blockIdx.x * 256 + threadIdx.x;
    if (i >= n4) return;
    float4 x = ((const float4*)X)[i];
    __nv_bfloat16 h[4], l[4];
    split1(x.x, h[0], l[0]); split1(x.y, h[1], l[1]);
    split1(x.z, h[2], l[2]); split1(x.w, h[3], l[3]);
    ((uint2*)H)[i] = *(uint2*)h;
    ((uint2*)L)[i] = *(uint2*)l;
}

// ---------------- pre-pass: transpose + split weights [K,N] -> [N,K] ----------------
__global__ void __launch_bounds__(256) wsplit_kernel(
    const float* __restrict__ W, __nv_bfloat16* __restrict__ Ht,
    __nv_bfloat16* __restrict__ Lt, int K, int N)
{
    int i = blockIdx.x * 256 + threadIdx.x;
    if (i >= K * N) return;
    int k = i / N, n = i % N;
    __nv_bfloat16 h, l;
    split1(W[i], h, l);
    Ht[(size_t)n * K + k] = h;
    Lt[(size_t)n * K + k] = l;
}

// ---------------- LayerNorm in place + optional 1/||.|| output ----------------
__global__ void __launch_bounds__(256) ln_kernel(float* __restrict__ X, float* __restrict__ rn)
{
    int row  = blockIdx.x * 8 + (threadIdx.x >> 5);
    int lane = threadIdx.x & 31;
    float* p = X + (size_t)row * DM + lane * 8;
    float4 u0 = *(const float4*)p;
    float4 u1 = *(const float4*)(p + 4);
    float s = u0.x + u0.y + u0.z + u0.w + u1.x + u1.y + u1.z + u1.w;
    s = warp_sum(s);
    float mu = s * (1.0f / DM);
    float d[8] = {u0.x-mu, u0.y-mu, u0.z-mu, u0.w-mu, u1.x-mu, u1.y-mu, u1.z-mu, u1.w-mu};
    float q = 0.f;
#pragma unroll
    for (int i = 0; i < 8; i++) q += d[i] * d[i];
    q = warp_sum(q);
    float inv = 1.0f / sqrtf(q * (1.0f / DM) + 1e-5f);
    float o[8];
#pragma unroll
    for (int i = 0; i < 8; i++) o[i] = d[i] * inv;
    *(float4*)p       = *(float4*)&o[0];
    *(float4*)(p + 4) = *(float4*)&o[4];
    if (rn && lane == 0) {
        float nrm = sqrtf(q) * inv;   // ||o||
        rn[row] = 1.0f / fmaxf(nrm, 1e-8f);
    }
}

// ---------------- fractional shift + causal window average ----------------
__global__ void __launch_bounds__(256) shiftbox_kernel(
    const float* __restrict__ A, float* __restrict__ Out,
    const float* __restrict__ theta)
{
    int gid = blockIdx.x * 256 + threadIdx.x;
    int row = gid >> 6;
    int d4  = gid & 63;
    int b = row / TT, t = row % TT;

    float th    = fminf(fmaxf(theta[0], -12.0f), 12.0f);
    float delta = 2.0f + 4.0f / (1.0f + expf(-th));
    float dl    = fminf(fmaxf(delta, 0.0f), (float)(TT - 1));
    float nf    = floorf(dl);
    float alpha = dl - nf;
    int   ni    = (int)nf;

    float center = fminf(fmaxf((float)t + delta, 0.0f), (float)t);
    int lo = max(0, (int)ceilf(center - 5.0f));
    int hi = min(t, (int)floorf(center + 5.0f));

    const float4* Av = (const float4*)A;
    float4 acc = make_float4(0.f, 0.f, 0.f, 0.f);
    float w0 = 1.0f - alpha, w1 = alpha;
    for (int tau = lo; tau <= hi; tau++) {
        int i0 = min(max(tau - ni, 0), TT - 1);
        int i1 = min(i0 + 1, TT - 1);
        float4 x0 = Av[(size_t)(b * TT + i0) * 64 + d4];
        float4 x1 = Av[(size_t)(b * TT + i1) * 64 + d4];
        acc.x += w0 * x0.x + w1 * x1.x;
        acc.y += w0 * x0.y + w1 * x1.y;
        acc.z += w0 * x0.z + w1 * x1.z;
        acc.w += w0 * x0.w + w1 * x1.w;
    }
    float scale = 1.0f / fmaxf((float)(hi - lo + 1), 1e-8f);
    acc.x *= scale; acc.y *= scale; acc.z *= scale; acc.w *= scale;
    ((float4*)Out)[(size_t)row * 64 + d4] = acc;
}

// ---------------- reciprocal L2 norm per row ----------------
__global__ void __launch_bounds__(256) rnorm_kernel(
    const float* __restrict__ X, float* __restrict__ rn)
{
    int row  = blockIdx.x * 8 + (threadIdx.x >> 5);
    int lane = threadIdx.x & 31;
    const float* p = X + (size_t)row * DM + lane * 8;
    float4 u0 = *(const float4*)p;
    float4 u1 = *(const float4*)(p + 4);
    float q = u0.x*u0.x + u0.y*u0.y + u0.z*u0.z + u0.w*u0.w
            + u1.x*u1.x + u1.y*u1.y + u1.z*u1.z + u1.w*u1.w;
    q = warp_sum(q);
    if (lane == 0) rn[row] = 1.0f / fmaxf(sqrtf(q), 1e-8f);
}

// ---------------- build x = [an, vn, an*vn] directly as bf16 hi/lo ----------------
__global__ void __launch_bounds__(256) buildx_kernel(
    const float* __restrict__ Actx, const float* __restrict__ V,
    const float* __restrict__ rna, const float* __restrict__ rnv,
    __nv_bfloat16* __restrict__ XH, __nv_bfloat16* __restrict__ XL)
{
    int gid = blockIdx.x * 256 + threadIdx.x;
    int row = gid >> 6;
    int d4  = gid & 63;
    float ra = rna[row], rv = rnv[row];
    float4 a = ((const float4*)Actx)[(size_t)row * 64 + d4];
    float4 v = ((const float4*)V)[(size_t)row * 64 + d4];
    float an[4] = {a.x*ra, a.y*ra, a.z*ra, a.w*ra};
    float vn[4] = {v.x*rv, v.y*rv, v.z*rv, v.w*rv};
    float pr[4] = {an[0]*vn[0], an[1]*vn[1], an[2]*vn[2], an[3]*vn[3]};

    size_t base = (size_t)row * XDIM;
    __nv_bfloat16 h[4], l[4];
#pragma unroll
    for (int i = 0; i < 4; i++) split1(an[i], h[i], l[i]);
    *(uint2*)&XH[base + 4*d4] = *(uint2*)h;
    *(uint2*)&XL[base + 4*d4] = *(uint2*)l;
#pragma unroll
    for (int i = 0; i < 4; i++) split1(vn[i], h[i], l[i]);
    *(uint2*)&XH[base + DM + 4*d4] = *(uint2*)h;
    *(uint2*)&XL[base + DM + 4*d4] = *(uint2*)l;
#pragma unroll
    for (int i = 0; i < 4; i++) split1(pr[i], h[i], l[i]);
    *(uint2*)&XH[base + 2*DM + 4*d4] = *(uint2*)h;
    *(uint2*)&XL[base + 2*DM + 4*d4] = *(uint2*)l;
}

// ---------------- final: logit = h@W2+b2, gate, blend (warp per row) ----------------
__global__ void __launch_bounds__(256) final_kernel(
    const float* __restrict__ H, const float* __restrict__ Actx,
    const float* __restrict__ V, const float* __restrict__ W2,
    const float* __restrict__ b2, float* __restrict__ Out)
{
    int row  = blockIdx.x * 8 + (threadIdx.x >> 5);
    int lane = threadIdx.x & 31;
    const float* hr = H + (size_t)row * HID;
    float s = 0.f;
#pragma unroll
    for (int i = 0; i < 32; i++) {
        int k = i * 32 + lane;
        s = fmaf(hr[k], W2[k], s);
    }
    s = warp_sum(s);
    float logit = fminf(fmaxf(s + b2[0], -12.0f), 12.0f);
    float g = 1.0f / (1.0f + expf(-logit));
    g = fminf(fmaxf(g, 0.05f), 0.95f);
    float om = 1.0f - g;

    const float4* av = (const float4*)(Actx + (size_t)row * DM);
    const float4* vv = (const float4*)(V    + (size_t)row * DM);
    float4*       ov = (float4*)(Out + (size_t)row * DM);
#pragma unroll
    for (int j = 0; j < 2; j++) {
        int d4 = lane * 2 + j;
        float4 a = av[d4], v = vv[d4];
        ov[d4] = make_float4(g*a.x + om*v.x, g*a.y + om*v.y,
                             g*a.z + om*v.z, g*a.w + om*v.w);
    }
}

// ---------------- launch ----------------
extern "C" void kernel_launch(void* const* d_in, const int* in_sizes, int n_in,
                              void* d_out, int out_size)
{
    const float* video = (const float*)d_in[0];
    const float* audio = (const float*)d_in[1];
    const float* Wv    = (const float*)d_in[2];
    const float* bv    = (const float*)d_in[3];
    const float* Wa    = (const float*)d_in[4];
    const float* ba    = (const float*)d_in[5];
    const float* theta = (const float*)d_in[6];
    const float* W1    = (const float*)d_in[7];
    const float* b1    = (const float*)d_in[8];
    const float* W2    = (const float*)d_in[9];
    const float* b2    = (const float*)d_in[10];
    float* out = (float*)d_out;

    float *pv, *pa, *pactx, *ph, *prnv, *prna;
    __nv_bfloat16 *pvh, *pvl, *pauh, *paul, *pxh, *pxl;
    __nv_bfloat16 *pwvh, *pwvl, *pwah, *pwal, *pw1h, *pw1l;
    cudaGetSymbolAddress((void**)&pv,    g_v);
    cudaGetSymbolAddress((void**)&pa,    g_a);
    cudaGetSymbolAddress((void**)&pactx, g_actx);
    cudaGetSymbolAddress((void**)&ph,    g_h);
    cudaGetSymbolAddress((void**)&prnv,  g_rnv);
    cudaGetSymbolAddress((void**)&prna,  g_rna);
    cudaGetSymbolAddress((void**)&pvh,   g_vh);
    cudaGetSymbolAddress((void**)&pvl,   g_vl);
    cudaGetSymbolAddress((void**)&pauh,  g_auh);
    cudaGetSymbolAddress((void**)&paul,  g_aul);
    cudaGetSymbolAddress((void**)&pxh,   g_xh);
    cudaGetSymbolAddress((void**)&pxl,   g_xl);
    cudaGetSymbolAddress((void**)&pwvh,  g_wvh);
    cudaGetSymbolAddress((void**)&pwvl,  g_wvl);
    cudaGetSymbolAddress((void**)&pwah,  g_wah);
    cudaGetSymbolAddress((void**)&pwal,  g_wal);
    cudaGetSymbolAddress((void**)&pw1h,  g_w1h);
    cudaGetSymbolAddress((void**)&pw1l,  g_w1l);

    cudaFuncSetAttribute(tc_gemm<false>, cudaFuncAttributeMaxDynamicSharedMemorySize, SMEM_TOTAL_GEMM);
    cudaFuncSetAttribute(tc_gemm<true>,  cudaFuncAttributeMaxDynamicSharedMemorySize, SMEM_TOTAL_GEMM);

    // ordered so a tc_gemm lands at the ncu-captured launch position (4th-5th)
    split_kernel<<<(MROWS*VDIM/4 + 255)/256, 256>>>(video, pvh, pvl, MROWS*VDIM/4);      // 1
    wsplit_kernel<<<(VDIM*DM + 255)/256, 256>>>(Wv, pwvh, pwvl, VDIM, DM);               // 2
    wsplit_kernel<<<(ADIM*DM + 255)/256, 256>>>(Wa, pwah, pwal, ADIM, DM);               // 3
    tc_gemm<false><<<dim3(DM/128, MROWS/128), 256, SMEM_TOTAL_GEMM>>>(                   // 4
        pvh, pvl, pwvh, pwvl, bv, pv, VDIM, DM);
    split_kernel<<<(MROWS*ADIM/4 + 255)/256, 256>>>(audio, pauh, paul, MROWS*ADIM/4);    // 5
    tc_gemm<false><<<dim3(DM/128, MROWS/128), 256, SMEM_TOTAL_GEMM>>>(                   // 6
        pauh, paul, pwah, pwal, ba, pa, ADIM, DM);
    wsplit_kernel<<<(XDIM*HID + 255)/256, 256>>>(W1, pw1h, pw1l, XDIM, HID);             // 7

    ln_kernel<<<MROWS/8, 256>>>(pv, prnv);                                               // 8
    ln_kernel<<<MROWS/8, 256>>>(pa, (float*)nullptr);                                    // 9
    shiftbox_kernel<<<(MROWS*64)/256, 256>>>(pa, pactx, theta);                          // 10
    rnorm_kernel<<<MROWS/8, 256>>>(pactx, prna);                                         // 11
    buildx_kernel<<<(MROWS*64)/256, 256>>>(pactx, pv, prna, prnv, pxh, pxl);             // 12
    tc_gemm<true><<<dim3(HID/128, MROWS/128), 256, SMEM_TOTAL_GEMM>>>(                   // 13
        pxh, pxl, pw1h, pw1l, b1, ph, XDIM, HID);
    final_kernel<<<MROWS/8, 256>>>(ph, pactx, pv, W2, b2, out);                          // 14
}

// round 9
// speedup vs baseline: 2.1223x; 2.0689x over previous
#include <cuda_runtime.h>
#include <cuda_fp16.h>
#include <math.h>
#include <stdint.h>

// ---------------- problem constants ----------------
#define BB 8
#define TT 2048
#define VDIM 1024
#define ADIM 768
#define DM 256
#define HID 1024
#define MROWS (BB*TT)     /* 16384 */
#define XDIM (3*DM)       /* 768 */

// ---------------- device scratch ----------------
__device__ __align__(16) float g_v[MROWS*DM];
__device__ __align__(16) float g_a[MROWS*DM];
__device__ __align__(16) float g_actx[MROWS*DM];
__device__ __align__(16) float g_h[MROWS*HID];
__device__ float g_rnv[MROWS];
__device__ float g_rna[MROWS];
// fp16 operands
__device__ __align__(16) __half g_vf[MROWS*VDIM];
__device__ __align__(16) __half g_af[MROWS*ADIM];
__device__ __align__(16) __half g_xf[MROWS*XDIM];
// transposed fp16 weights [N,K]
__device__ __align__(16) __half g_wv[DM*VDIM];
__device__ __align__(16) __half g_wa[DM*ADIM];
__device__ __align__(16) __half g_w1[HID*XDIM];

// ---------------- helpers ----------------
__device__ __forceinline__ float warp_sum(float v) {
#pragma unroll
    for (int o = 16; o > 0; o >>= 1) v += __shfl_xor_sync(0xffffffffu, v, o);
    return v;
}
__device__ __forceinline__ float gelu_exact(float x) {
    return 0.5f * x * (1.0f + erff(x * 0.70710678118654752f));
}
__device__ __forceinline__ void cp_async16(uint32_t dst, const void* src) {
    asm volatile("cp.async.cg.shared.global [%0], [%1], 16;" :: "r"(dst), "l"(src));
}
__device__ __forceinline__ void cp_commit() {
    asm volatile("cp.async.commit_group;" ::: "memory");
}
template<int N> __device__ __forceinline__ void cp_wait() {
    asm volatile("cp.async.wait_group %0;" :: "n"(N) : "memory");
}
__device__ __forceinline__ uint32_t smem_u32(const void* p) {
    uint32_t a;
    asm("{ .reg .u64 t; cvta.to.shared.u64 t, %1; cvt.u32.u64 %0, t; }" : "=r"(a) : "l"(p));
    return a;
}
// mma.sync m16n8k16 fp16 (row.col), fp32 accum
__device__ __forceinline__ void mma_f16(float* c, const uint32_t* a, const uint32_t* b) {
    asm volatile(
        "mma.sync.aligned.m16n8k16.row.col.f32.f16.f16.f32 "
        "{%0,%1,%2,%3}, {%4,%5,%6,%7}, {%8,%9}, {%0,%1,%2,%3};"
        : "+f"(c[0]), "+f"(c[1]), "+f"(c[2]), "+f"(c[3])
        : "r"(a[0]), "r"(a[1]), "r"(a[2]), "r"(a[3]), "r"(b[0]), "r"(b[1]));
}
__device__ __forceinline__ void ldsm_x4(uint32_t* r, uint32_t addr) {
    asm volatile("ldmatrix.sync.aligned.m8n8.x4.shared.b16 {%0,%1,%2,%3}, [%4];"
        : "=r"(r[0]), "=r"(r[1]), "=r"(r[2]), "=r"(r[3]) : "r"(addr));
}

// ---------------- mma.sync fp16 GEMM (3-stage pipeline, 2 CTAs/SM) ----------------
// C[M,N] = A[M,K] @ B^T, B stored [N,K] K-major.
// Block tile 128x128, BK=32, 8 warps (4 M x 2 N), warp tile 32x64.
#define SROW 40                        /* smem row stride in fp16 (80 bytes) */
#define SROWB (SROW*2)                 /* 80 bytes */
#define OP_BYTES (128*SROWB)           /* 10240 B per operand */
#define STAGE_BYTES (2*OP_BYTES)       /* 20480 B */
#define NSTAGE 3
#define SMEM_TOTAL_GEMM (NSTAGE*STAGE_BYTES) /* 61440 B */

template<bool GELU>
__global__ void __launch_bounds__(256, 2) tc_gemm(
    const __half* __restrict__ A, const __half* __restrict__ B,
    const float* __restrict__ bias, float* __restrict__ C, int K, int N)
{
    extern __shared__ __half smem[];
    uint32_t sbase = smem_u32(smem);
    const int tid    = threadIdx.x;
    const int wid    = tid >> 5;
    const int lane   = tid & 31;
    const int warp_m = wid >> 1;          // 0..3
    const int warp_n = wid & 1;           // 0..1
    const int lr     = lane >> 2;         // 0..7
    const int lc     = lane & 3;          // 0..3
    const int lr8    = lane & 7;          // 0..7
    const int lg     = lane >> 3;         // 0..3 (ldmatrix group)
    const int row0   = blockIdx.y * 128;
    const int col0   = blockIdx.x * 128;

    const __half* Ap = A + (size_t)row0 * K;
    const __half* Bp = B + (size_t)col0 * K;

    const int nk = K >> 5;   // BK=32 iterations

    // ldmatrix per-thread base offsets (bytes, within one operand tile)
    uint32_t aoff[2], boff[4];
#pragma unroll
    for (int im = 0; im < 2; im++)
        aoff[im] = (uint32_t)((warp_m*32 + im*16 + (lg & 1)*8 + lr8) * SROWB + ((lg >> 1)*8) * 2);
#pragma unroll
    for (int ip = 0; ip < 4; ip++)
        boff[ip] = (uint32_t)((warp_n*64 + ip*16 + (lg >> 1)*8 + lr8) * SROWB + ((lg & 1)*8) * 2);

    // cp.async stage loader: 128 rows x 32 cols fp16 (64B) per operand
    auto load_stage = [&](int kt) {
        uint32_t sb = sbase + (uint32_t)(kt % NSTAGE) * STAGE_BYTES;
        int koff = kt * 32;
#pragma unroll
        for (int i = 0; i < 2; i++) {
            int id = tid + i * 256;           // 0..511
            int r  = id >> 2;                 // 0..127
            int c  = id & 3;                  // 0..3 (16B chunks)
            uint32_t soff = (uint32_t)(r * SROWB + c * 16);
            size_t   goff = (size_t)r * K + koff + c * 8;
            cp_async16(sb +            soff, Ap + goff);
            cp_async16(sb + OP_BYTES + soff, Bp + goff);
        }
        cp_commit();
    };

    float acc[2][8][4];
#pragma unroll
    for (int im = 0; im < 2; im++)
#pragma unroll
        for (int in = 0; in < 8; in++)
#pragma unroll
            for (int j = 0; j < 4; j++) acc[im][in][j] = 0.f;

    load_stage(0);
    load_stage(1);

    for (int k = 0; k < nk; k++) {
        if (k == nk - 1) cp_wait<0>();
        else             cp_wait<1>();
        __syncthreads();
        if (k + 2 < nk) load_stage(k + 2);

        uint32_t sA = sbase + (uint32_t)(k % NSTAGE) * STAGE_BYTES;
        uint32_t sB = sA + OP_BYTES;

#pragma unroll
        for (int kk = 0; kk < 2; kk++) {
            uint32_t kb = (uint32_t)(kk * 32);   // 16 fp16 = 32 bytes
            uint32_t a[2][4], b[8][2];
#pragma unroll
            for (int im = 0; im < 2; im++)
                ldsm_x4(a[im], sA + aoff[im] + kb);
#pragma unroll
            for (int ip = 0; ip < 4; ip++) {
                uint32_t t[4];
                ldsm_x4(t, sB + boff[ip] + kb);
                b[2*ip][0] = t[0]; b[2*ip][1] = t[1];
                b[2*ip+1][0] = t[2]; b[2*ip+1][1] = t[3];
            }
#pragma unroll
            for (int im = 0; im < 2; im++)
#pragma unroll
                for (int in = 0; in < 8; in++)
                    mma_f16(acc[im][in], a[im], b[in]);
        }
    }

    // epilogue: + bias, optional gelu
#pragma unroll
    for (int im = 0; im < 2; im++) {
        int r0 = row0 + warp_m * 32 + im * 16 + lr;
#pragma unroll
        for (int in = 0; in < 8; in++) {
            int c = col0 + warp_n * 64 + in * 8 + lc * 2;
            float b0 = bias[c], b1 = bias[c + 1];
            float2 v0, v1;
            v0.x = acc[im][in][0] + b0; v0.y = acc[im][in][1] + b1;
            v1.x = acc[im][in][2] + b0; v1.y = acc[im][in][3] + b1;
            if (GELU) {
                v0.x = gelu_exact(v0.x); v0.y = gelu_exact(v0.y);
                v1.x = gelu_exact(v1.x); v1.y = gelu_exact(v1.y);
            }
            *(float2*)&C[(size_t)(r0    ) * N + c] = v0;
            *(float2*)&C[(size_t)(r0 + 8) * N + c] = v1;
        }
    }
}

// ---------------- pre-pass: convert fp32 -> fp16 ----------------
__global__ void __launch_bounds__(256) cvt_kernel(
    const float* __restrict__ X, __half* __restrict__ H, int n4)
{
    int i = blockIdx.x * 256 + threadIdx.x;
    if (i >= n4) return;
    float4 x = ((const float4*)X)[i];
    __half h[4] = {__float2half(x.x), __float2half(x.y),
                   __float2half(x.z), __float2half(x.w)};
    ((uint2*)H)[i] = *(uint2*)h;
}

// ---------------- pre-pass: transpose + convert weights [K,N] -> [N,K] fp16 ----------------
__global__ void __launch_bounds__(256) wcvt_kernel(
    const float* __restrict__ W, __half* __restrict__ Ht, int K, int N)
{
    int i = blockIdx.x * 256 + threadIdx.x;
    if (i >= K * N) return;
    int k = i / N, n = i % N;
    Ht[(size_t)n * K + k] = __float2half(W[i]);
}

// ---------------- LayerNorm in place + optional 1/||.|| output ----------------
__global__ void __launch_bounds__(256) ln_kernel(float* __restrict__ X, float* __restrict__ rn)
{
    int row  = blockIdx.x * 8 + (threadIdx.x >> 5);
    int lane = threadIdx.x & 31;
    float* p = X + (size_t)row * DM + lane * 8;
    float4 u0 = *(const float4*)p;
    float4 u1 = *(const float4*)(p + 4);
    float s = u0.x + u0.y + u0.z + u0.w + u1.x + u1.y + u1.z + u1.w;
    s = warp_sum(s);
    float mu = s * (1.0f / DM);
    float d[8] = {u0.x-mu, u0.y-mu, u0.z-mu, u0.w-mu, u1.x-mu, u1.y-mu, u1.z-mu, u1.w-mu};
    float q = 0.f;
#pragma unroll
    for (int i = 0; i < 8; i++) q += d[i] * d[i];
    q = warp_sum(q);
    float inv = 1.0f / sqrtf(q * (1.0f / DM) + 1e-5f);
    float o[8];
#pragma unroll
    for (int i = 0; i < 8; i++) o[i] = d[i] * inv;
    *(float4*)p       = *(float4*)&o[0];
    *(float4*)(p + 4) = *(float4*)&o[4];
    if (rn && lane == 0) {
        float nrm = sqrtf(q) * inv;   // ||o||
        rn[row] = 1.0f / fmaxf(nrm, 1e-8f);
    }
}

// ---------------- fractional shift + causal window average ----------------
__global__ void __launch_bounds__(256) shiftbox_kernel(
    const float* __restrict__ A, float* __restrict__ Out,
    const float* __restrict__ theta)
{
    int gid = blockIdx.x * 256 + threadIdx.x;
    int row = gid >> 6;
    int d4  = gid & 63;
    int b = row / TT, t = row % TT;

    float th    = fminf(fmaxf(theta[0], -12.0f), 12.0f);
    float delta = 2.0f + 4.0f / (1.0f + expf(-th));
    float dl    = fminf(fmaxf(delta, 0.0f), (float)(TT - 1));
    float nf    = floorf(dl);
    float alpha = dl - nf;
    int   ni    = (int)nf;

    float center = fminf(fmaxf((float)t + delta, 0.0f), (float)t);
    int lo = max(0, (int)ceilf(center - 5.0f));
    int hi = min(t, (int)floorf(center + 5.0f));

    const float4* Av = (const float4*)A;
    float4 acc = make_float4(0.f, 0.f, 0.f, 0.f);
    float w0 = 1.0f - alpha, w1 = alpha;
    for (int tau = lo; tau <= hi; tau++) {
        int i0 = min(max(tau - ni, 0), TT - 1);
        int i1 = min(i0 + 1, TT - 1);
        float4 x0 = Av[(size_t)(b * TT + i0) * 64 + d4];
        float4 x1 = Av[(size_t)(b * TT + i1) * 64 + d4];
        acc.x += w0 * x0.x + w1 * x1.x;
        acc.y += w0 * x0.y + w1 * x1.y;
        acc.z += w0 * x0.z + w1 * x1.z;
        acc.w += w0 * x0.w + w1 * x1.w;
    }
    float scale = 1.0f / fmaxf((float)(hi - lo + 1), 1e-8f);
    acc.x *= scale; acc.y *= scale; acc.z *= scale; acc.w *= scale;
    ((float4*)Out)[(size_t)row * 64 + d4] = acc;
}

// ---------------- reciprocal L2 norm per row ----------------
__global__ void __launch_bounds__(256) rnorm_kernel(
    const float* __restrict__ X, float* __restrict__ rn)
{
    int row  = blockIdx.x * 8 + (threadIdx.x >> 5);
    int lane = threadIdx.x & 31;
    const float* p = X + (size_t)row * DM + lane * 8;
    float4 u0 = *(const float4*)p;
    float4 u1 = *(const float4*)(p + 4);
    float q = u0.x*u0.x + u0.y*u0.y + u0.z*u0.z + u0.w*u0.w
            + u1.x*u1.x + u1.y*u1.y + u1.z*u1.z + u1.w*u1.w;
    q = warp_sum(q);
    if (lane == 0) rn[row] = 1.0f / fmaxf(sqrtf(q), 1e-8f);
}

// ---------------- build x = [an, vn, an*vn] directly as fp16 ----------------
__global__ void __launch_bounds__(256) buildx_kernel(
    const float* __restrict__ Actx, const float* __restrict__ V,
    const float* __restrict__ rna, const float* __restrict__ rnv,
    __half* __restrict__ XH)
{
    int gid = blockIdx.x * 256 + threadIdx.x;
    int row = gid >> 6;
    int d4  = gid & 63;
    float ra = rna[row], rv = rnv[row];
    float4 a = ((const float4*)Actx)[(size_t)row * 64 + d4];
    float4 v = ((const float4*)V)[(size_t)row * 64 + d4];
    float an[4] = {a.x*ra, a.y*ra, a.z*ra, a.w*ra};
    float vn[4] = {v.x*rv, v.y*rv, v.z*rv, v.w*rv};
    float pr[4] = {an[0]*vn[0], an[1]*vn[1], an[2]*vn[2], an[3]*vn[3]};

    size_t base = (size_t)row * XDIM;
    __half h[4];
#pragma unroll
    for (int i = 0; i < 4; i++) h[i] = __float2half(an[i]);
    *(uint2*)&XH[base + 4*d4] = *(uint2*)h;
#pragma unroll
    for (int i = 0; i < 4; i++) h[i] = __float2half(vn[i]);
    *(uint2*)&XH[base + DM + 4*d4] = *(uint2*)h;
#pragma unroll
    for (int i = 0; i < 4; i++) h[i] = __float2half(pr[i]);
    *(uint2*)&XH[base + 2*DM + 4*d4] = *(uint2*)h;
}

// ---------------- final: logit = h@W2+b2, gate, blend (warp per row) ----------------
__global__ void __launch_bounds__(256) final_kernel(
    const float* __restrict__ H, const float* __restrict__ Actx,
    const float* __restrict__ V, const float* __restrict__ W2,
    const float* __restrict__ b2, float* __restrict__ Out)
{
    int row  = blockIdx.x * 8 + (threadIdx.x >> 5);
    int lane = threadIdx.x & 31;
    const float* hr = H + (size_t)row * HID;
    float s = 0.f;
#pragma unroll
    for (int i = 0; i < 32; i++) {
        int k = i * 32 + lane;
        s = fmaf(hr[k], W2[k], s);
    }
    s = warp_sum(s);
    float logit = fminf(fmaxf(s + b2[0], -12.0f), 12.0f);
    float g = 1.0f / (1.0f + expf(-logit));
    g = fminf(fmaxf(g, 0.05f), 0.95f);
    float om = 1.0f - g;

    const float4* av = (const float4*)(Actx + (size_t)row * DM);
    const float4* vv = (const float4*)(V    + (size_t)row * DM);
    float4*       ov = (float4*)(Out + (size_t)row * DM);
#pragma unroll
    for (int j = 0; j < 2; j++) {
        int d4 = lane * 2 + j;
        float4 a = av[d4], v = vv[d4];
        ov[d4] = make_float4(g*a.x + om*v.x, g*a.y + om*v.y,
                             g*a.z + om*v.z, g*a.w + om*v.w);
    }
}

// ---------------- launch ----------------
extern "C" void kernel_launch(void* const* d_in, const int* in_sizes, int n_in,
                              void* d_out, int out_size)
{
    const float* video = (const float*)d_in[0];
    const float* audio = (const float*)d_in[1];
    const float* Wv    = (const float*)d_in[2];
    const float* bv    = (const float*)d_in[3];
    const float* Wa    = (const float*)d_in[4];
    const float* ba    = (const float*)d_in[5];
    const float* theta = (const float*)d_in[6];
    const float* W1    = (const float*)d_in[7];
    const float* b1    = (const float*)d_in[8];
    const float* W2    = (const float*)d_in[9];
    const float* b2    = (const float*)d_in[10];
    float* out = (float*)d_out;

    float *pv, *pa, *pactx, *ph, *prnv, *prna;
    __half *pvf, *paf, *pxf, *pwv, *pwa, *pw1;
    cudaGetSymbolAddress((void**)&pv,    g_v);
    cudaGetSymbolAddress((void**)&pa,    g_a);
    cudaGetSymbolAddress((void**)&pactx, g_actx);
    cudaGetSymbolAddress((void**)&ph,    g_h);
    cudaGetSymbolAddress((void**)&prnv,  g_rnv);
    cudaGetSymbolAddress((void**)&prna,  g_rna);
    cudaGetSymbolAddress((void**)&pvf,   g_vf);
    cudaGetSymbolAddress((void**)&paf,   g_af);
    cudaGetSymbolAddress((void**)&pxf,   g_xf);
    cudaGetSymbolAddress((void**)&pwv,   g_wv);
    cudaGetSymbolAddress((void**)&pwa,   g_wa);
    cudaGetSymbolAddress((void**)&pw1,   g_w1);

    cudaFuncSetAttribute(tc_gemm<false>, cudaFuncAttributeMaxDynamicSharedMemorySize, SMEM_TOTAL_GEMM);
    cudaFuncSetAttribute(tc_gemm<true>,  cudaFuncAttributeMaxDynamicSharedMemorySize, SMEM_TOTAL_GEMM);

    // ordered so a tc_gemm lands at the ncu-captured launch position (4th-5th)
    cvt_kernel<<<(MROWS*VDIM/4 + 255)/256, 256>>>(video, pvf, MROWS*VDIM/4);             // 1
    wcvt_kernel<<<(VDIM*DM + 255)/256, 256>>>(Wv, pwv, VDIM, DM);                        // 2
    wcvt_kernel<<<(ADIM*DM + 255)/256, 256>>>(Wa, pwa, ADIM, DM);                        // 3
    tc_gemm<false><<<dim3(DM/128, MROWS/128), 256, SMEM_TOTAL_GEMM>>>(                   // 4
        pvf, pwv, bv, pv, VDIM, DM);
    cvt_kernel<<<(MROWS*ADIM/4 + 255)/256, 256>>>(audio, paf, MROWS*ADIM/4);             // 5
    tc_gemm<false><<<dim3(DM/128, MROWS/128), 256, SMEM_TOTAL_GEMM>>>(                   // 6
        paf, pwa, ba, pa, ADIM, DM);
    wcvt_kernel<<<(XDIM*HID + 255)/256, 256>>>(W1, pw1, XDIM, HID);                      // 7

    ln_kernel<<<MROWS/8, 256>>>(pv, prnv);                                               // 8
    ln_kernel<<<MROWS/8, 256>>>(pa, (float*)nullptr);                                    // 9
    shiftbox_kernel<<<(MROWS*64)/256, 256>>>(pa, pactx, theta);                          // 10
    rnorm_kernel<<<MROWS/8, 256>>>(pactx, prna);                                         // 11
    buildx_kernel<<<(MROWS*64)/256, 256>>>(pactx, pv, prna, prnv, pxf);                  // 12
    tc_gemm<true><<<dim3(HID/128, MROWS/128), 256, SMEM_TOTAL_GEMM>>>(                   // 13
        pxf, pw1, b1, ph, XDIM, HID);
    final_kernel<<<MROWS/8, 256>>>(ph, pactx, pv, W2, b2, out);                          // 14
}

// round 13
// speedup vs baseline: 2.1892x; 1.0315x over previous
#include <cuda_runtime.h>
#include <cuda_fp16.h>
#include <math.h>
#include <stdint.h>

// ---------------- problem constants ----------------
#define BB 8
#define TT 2048
#define VDIM 1024
#define ADIM 768
#define DM 256
#define HID 1024
#define MROWS (BB*TT)     /* 16384 */
#define XDIM (3*DM)       /* 768 */

// ---------------- device scratch ----------------
__device__ __align__(16) float g_v[MROWS*DM];
__device__ __align__(16) float g_a[MROWS*DM];
__device__ __align__(16) float g_actx[MROWS*DM];
__device__ __align__(16) float g_h[MROWS*HID];
__device__ float g_rnv[MROWS];
// fp16 operands
__device__ __align__(16) __half g_vf[MROWS*VDIM];
__device__ __align__(16) __half g_af[MROWS*ADIM];
__device__ __align__(16) __half g_xf[MROWS*XDIM];
// transposed fp16 weights [N,K]
__device__ __align__(16) __half g_wv[DM*VDIM];
__device__ __align__(16) __half g_wa[DM*ADIM];
__device__ __align__(16) __half g_w1[HID*XDIM];

// ---------------- helpers ----------------
__device__ __forceinline__ float warp_sum(float v) {
#pragma unroll
    for (int o = 16; o > 0; o >>= 1) v += __shfl_xor_sync(0xffffffffu, v, o);
    return v;
}
__device__ __forceinline__ float gelu_exact(float x) {
    return 0.5f * x * (1.0f + erff(x * 0.70710678118654752f));
}
__device__ __forceinline__ void cp_async16(uint32_t dst, const void* src) {
    asm volatile("cp.async.cg.shared.global [%0], [%1], 16;" :: "r"(dst), "l"(src));
}
__device__ __forceinline__ void cp_commit() {
    asm volatile("cp.async.commit_group;" ::: "memory");
}
template<int N> __device__ __forceinline__ void cp_wait() {
    asm volatile("cp.async.wait_group %0;" :: "n"(N) : "memory");
}
__device__ __forceinline__ uint32_t smem_u32(const void* p) {
    uint32_t a;
    asm("{ .reg .u64 t; cvta.to.shared.u64 t, %1; cvt.u32.u64 %0, t; }" : "=r"(a) : "l"(p));
    return a;
}
// mma.sync m16n8k16 fp16 (row.col), fp32 accum
__device__ __forceinline__ void mma_f16(float* c, const uint32_t* a, const uint32_t* b) {
    asm volatile(
        "mma.sync.aligned.m16n8k16.row.col.f32.f16.f16.f32 "
        "{%0,%1,%2,%3}, {%4,%5,%6,%7}, {%8,%9}, {%0,%1,%2,%3};"
        : "+f"(c[0]), "+f"(c[1]), "+f"(c[2]), "+f"(c[3])
        : "r"(a[0]), "r"(a[1]), "r"(a[2]), "r"(a[3]), "r"(b[0]), "r"(b[1]));
}
__device__ __forceinline__ void ldsm_x4(uint32_t* r, uint32_t addr) {
    asm volatile("ldmatrix.sync.aligned.m8n8.x4.shared.b16 {%0,%1,%2,%3}, [%4];"
        : "=r"(r[0]), "=r"(r[1]), "=r"(r[2]), "=r"(r[3]) : "r"(addr));
}

// ---------------- mma.sync fp16 GEMM (BK=64, 3-stage, 2 CTAs/SM) ----------------
// C[M,N] = A[M,K] @ B^T, B stored [N,K] K-major.
// Block tile 128x128, BK=64, 8 warps (4 M x 2 N), warp tile 32x64.
#define SROWB 144                      /* smem row stride bytes: 128 data + 16 pad */
#define OP_BYTES (128*SROWB)           /* 18432 B per operand */
#define STAGE_BYTES (2*OP_BYTES)       /* 36864 B */
#define NSTAGE 3
#define SMEM_TOTAL_GEMM (NSTAGE*STAGE_BYTES) /* 110592 B */

template<bool GELU>
__global__ void __launch_bounds__(256, 2) tc_gemm(
    const __half* __restrict__ A, const __half* __restrict__ B,
    const float* __restrict__ bias, float* __restrict__ C, int K, int N)
{
    extern __shared__ __half smem[];
    uint32_t sbase = smem_u32(smem);
    const int tid    = threadIdx.x;
    const int wid    = tid >> 5;
    const int lane   = tid & 31;
    const int warp_m = wid >> 1;          // 0..3
    const int warp_n = wid & 1;           // 0..1
    const int lr     = lane >> 2;         // 0..7
    const int lc     = lane & 3;          // 0..3
    const int lr8    = lane & 7;          // 0..7
    const int lg     = lane >> 3;         // 0..3 (ldmatrix group)
    const int row0   = blockIdx.y * 128;
    const int col0   = blockIdx.x * 128;

    const __half* Ap = A + (size_t)row0 * K;
    const __half* Bp = B + (size_t)col0 * K;

    const int nk = K >> 6;   // BK=64 iterations

    // ldmatrix per-thread base offsets (bytes, within one operand tile)
    uint32_t aoff[2], boff[4];
#pragma unroll
    for (int im = 0; im < 2; im++)
        aoff[im] = (uint32_t)((warp_m*32 + im*16 + (lg & 1)*8 + lr8) * SROWB + ((lg >> 1)*8) * 2);
#pragma unroll
    for (int ip = 0; ip < 4; ip++)
        boff[ip] = (uint32_t)((warp_n*64 + ip*16 + (lg >> 1)*8 + lr8) * SROWB + ((lg & 1)*8) * 2);

    // cp.async stage loader: 128 rows x 64 cols fp16 (128 B) per operand, 8x16B per row
    auto load_stage = [&](int kt) {
        uint32_t sb = sbase + (uint32_t)(kt % NSTAGE) * STAGE_BYTES;
        int koff = kt * 64;
#pragma unroll
        for (int i = 0; i < 4; i++) {
            int id = tid + i * 256;           // 0..1023
            int r  = id >> 3;                 // 0..127
            int c  = id & 7;                  // 0..7 (16B chunks)
            uint32_t soff = (uint32_t)(r * SROWB + c * 16);
            size_t   goff = (size_t)r * K + koff + c * 8;
            cp_async16(sb +            soff, Ap + goff);
            cp_async16(sb + OP_BYTES + soff, Bp + goff);
        }
        cp_commit();
    };

    float acc[2][8][4];
#pragma unroll
    for (int im = 0; im < 2; im++)
#pragma unroll
        for (int in = 0; in < 8; in++)
#pragma unroll
            for (int j = 0; j < 4; j++) acc[im][in][j] = 0.f;

    load_stage(0);
    load_stage(1);

    for (int k = 0; k < nk; k++) {
        if (k == nk - 1) cp_wait<0>();
        else             cp_wait<1>();
        __syncthreads();
        // safe: every warp passed barrier => finished MMA of iter k-1,
        // whose buffer (k-1)%3 == (k+2)%3 is being overwritten
        if (k + 2 < nk) load_stage(k + 2);

        uint32_t sA = sbase + (uint32_t)(k % NSTAGE) * STAGE_BYTES;
        uint32_t sB = sA + OP_BYTES;

#pragma unroll
        for (int kk = 0; kk < 4; kk++) {
            uint32_t kb = (uint32_t)(kk * 32);   // 16 fp16 = 32 bytes per k16 step
            uint32_t a[2][4], b[8][2];
#pragma unroll
            for (int im = 0; im < 2; im++)
                ldsm_x4(a[im], sA + aoff[im] + kb);
#pragma unroll
            for (int ip = 0; ip < 4; ip++) {
                uint32_t t[4];
                ldsm_x4(t, sB + boff[ip] + kb);
                b[2*ip][0] = t[0]; b[2*ip][1] = t[1];
                b[2*ip+1][0] = t[2]; b[2*ip+1][1] = t[3];
            }
#pragma unroll
            for (int im = 0; im < 2; im++)
#pragma unroll
                for (int in = 0; in < 8; in++)
                    mma_f16(acc[im][in], a[im], b[in]);
        }
    }

    // epilogue: + bias, optional gelu
#pragma unroll
    for (int im = 0; im < 2; im++) {
        int r0 = row0 + warp_m * 32 + im * 16 + lr;
#pragma unroll
        for (int in = 0; in < 8; in++) {
            int c = col0 + warp_n * 64 + in * 8 + lc * 2;
            float b0 = bias[c], b1 = bias[c + 1];
            float2 v0, v1;
            v0.x = acc[im][in][0] + b0; v0.y = acc[im][in][1] + b1;
            v1.x = acc[im][in][2] + b0; v1.y = acc[im][in][3] + b1;
            if (GELU) {
                v0.x = gelu_exact(v0.x); v0.y = gelu_exact(v0.y);
                v1.x = gelu_exact(v1.x); v1.y = gelu_exact(v1.y);
            }
            *(float2*)&C[(size_t)(r0    ) * N + c] = v0;
            *(float2*)&C[(size_t)(r0 + 8) * N + c] = v1;
        }
    }
}

// ---------------- pre-pass: convert fp32 -> fp16 ----------------
__global__ void __launch_bounds__(256) cvt_kernel(
    const float* __restrict__ X, __half* __restrict__ H, int n4)
{
    int i = blockIdx.x * 256 + threadIdx.x;
    if (i >= n4) return;
    float4 x = ((const float4*)X)[i];
    __half h[4] = {__float2half(x.x), __float2half(x.y),
                   __float2half(x.z), __float2half(x.w)};
    ((uint2*)H)[i] = *(uint2*)h;
}

// ---------------- pre-pass: transpose + convert weights [K,N] -> [N,K] fp16 ----------------
__global__ void __launch_bounds__(256) wcvt_kernel(
    const float* __restrict__ W, __half* __restrict__ Ht, int K, int N)
{
    int i = blockIdx.x * 256 + threadIdx.x;
    if (i >= K * N) return;
    int k = i / N, n = i % N;
    Ht[(size_t)n * K + k] = __float2half(W[i]);
}

// ---------------- LayerNorm in place + optional 1/||.|| output ----------------
__global__ void __launch_bounds__(256) ln_kernel(float* __restrict__ X, float* __restrict__ rn)
{
    int row  = blockIdx.x * 8 + (threadIdx.x >> 5);
    int lane = threadIdx.x & 31;
    float* p = X + (size_t)row * DM + lane * 8;
    float4 u0 = *(const float4*)p;
    float4 u1 = *(const float4*)(p + 4);
    float s = u0.x + u0.y + u0.z + u0.w + u1.x + u1.y + u1.z + u1.w;
    s = warp_sum(s);
    float mu = s * (1.0f / DM);
    float d[8] = {u0.x-mu, u0.y-mu, u0.z-mu, u0.w-mu, u1.x-mu, u1.y-mu, u1.z-mu, u1.w-mu};
    float q = 0.f;
#pragma unroll
    for (int i = 0; i < 8; i++) q += d[i] * d[i];
    q = warp_sum(q);
    float inv = 1.0f / sqrtf(q * (1.0f / DM) + 1e-5f);
    float o[8];
#pragma unroll
    for (int i = 0; i < 8; i++) o[i] = d[i] * inv;
    *(float4*)p       = *(float4*)&o[0];
    *(float4*)(p + 4) = *(float4*)&o[4];
    if (rn && lane == 0) {
        float nrm = sqrtf(q) * inv;   // ||o||
        rn[row] = 1.0f / fmaxf(nrm, 1e-8f);
    }
}

// ---------------- fractional shift + causal window average ----------------
__global__ void __launch_bounds__(256) shiftbox_kernel(
    const float* __restrict__ A, float* __restrict__ Out,
    const float* __restrict__ theta)
{
    int gid = blockIdx.x * 256 + threadIdx.x;
    int row = gid >> 6;
    int d4  = gid & 63;
    int b = row / TT, t = row % TT;

    float th    = fminf(fmaxf(theta[0], -12.0f), 12.0f);
    float delta = 2.0f + 4.0f / (1.0f + expf(-th));
    float dl    = fminf(fmaxf(delta, 0.0f), (float)(TT - 1));
    float nf    = floorf(dl);
    float alpha = dl - nf;
    int   ni    = (int)nf;

    float center = fminf(fmaxf((float)t + delta, 0.0f), (float)t);
    int lo = max(0, (int)ceilf(center - 5.0f));
    int hi = min(t, (int)floorf(center + 5.0f));

    const float4* Av = (const float4*)A;
    float4 acc = make_float4(0.f, 0.f, 0.f, 0.f);
    float w0 = 1.0f - alpha, w1 = alpha;
    for (int tau = lo; tau <= hi; tau++) {
        int i0 = min(max(tau - ni, 0), TT - 1);
        int i1 = min(i0 + 1, TT - 1);
        float4 x0 = Av[(size_t)(b * TT + i0) * 64 + d4];
        float4 x1 = Av[(size_t)(b * TT + i1) * 64 + d4];
        acc.x += w0 * x0.x + w1 * x1.x;
        acc.y += w0 * x0.y + w1 * x1.y;
        acc.z += w0 * x0.z + w1 * x1.z;
        acc.w += w0 * x0.w + w1 * x1.w;
    }
    float scale = 1.0f / fmaxf((float)(hi - lo + 1), 1e-8f);
    acc.x *= scale; acc.y *= scale; acc.z *= scale; acc.w *= scale;
    ((float4*)Out)[(size_t)row * 64 + d4] = acc;
}

// ---------------- fused: rnorm(actx) + build x = [an, vn, an*vn] fp16 (warp/row) ----------------
__global__ void __launch_bounds__(256) buildx_kernel(
    const float* __restrict__ Actx, const float* __restrict__ V,
    const float* __restrict__ rnv, __half* __restrict__ XH)
{
    int row  = blockIdx.x * 8 + (threadIdx.x >> 5);
    int lane = threadIdx.x & 31;

    const float* ar = Actx + (size_t)row * DM + lane * 8;
    const float* vr = V    + (size_t)row * DM + lane * 8;
    float a[8], v[8];
    *(float4*)&a[0] = *(const float4*)ar;
    *(float4*)&a[4] = *(const float4*)(ar + 4);
    *(float4*)&v[0] = *(const float4*)vr;
    *(float4*)&v[4] = *(const float4*)(vr + 4);

    float q = 0.f;
#pragma unroll
    for (int i = 0; i < 8; i++) q += a[i] * a[i];
    q = warp_sum(q);
    float ra = 1.0f / fmaxf(sqrtf(q), 1e-8f);
    float rv = rnv[row];

    __half an[8], vn[8], pr[8];
#pragma unroll
    for (int i = 0; i < 8; i++) {
        float anf = a[i] * ra, vnf = v[i] * rv;
        an[i] = __float2half(anf);
        vn[i] = __float2half(vnf);
        pr[i] = __float2half(anf * vnf);
    }
    size_t base = (size_t)row * XDIM + lane * 8;
    *(uint4*)&XH[base]          = *(uint4*)an;
    *(uint4*)&XH[base + DM]     = *(uint4*)vn;
    *(uint4*)&XH[base + 2*DM]   = *(uint4*)pr;
}

// ---------------- final: logit = h@W2+b2, gate, blend (warp per row) ----------------
__global__ void __launch_bounds__(256) final_kernel(
    const float* __restrict__ H, const float* __restrict__ Actx,
    const float* __restrict__ V, const float* __restrict__ W2,
    const float* __restrict__ b2, float* __restrict__ Out)
{
    int row  = blockIdx.x * 8 + (threadIdx.x >> 5);
    int lane = threadIdx.x & 31;
    const float* hr = H + (size_t)row * HID;
    float s = 0.f;
#pragma unroll
    for (int i = 0; i < 32; i++) {
        int k = i * 32 + lane;
        s = fmaf(hr[k], W2[k], s);
    }
    s = warp_sum(s);
    float logit = fminf(fmaxf(s + b2[0], -12.0f), 12.0f);
    float g = 1.0f / (1.0f + expf(-logit));
    g = fminf(fmaxf(g, 0.05f), 0.95f);
    float om = 1.0f - g;

    const float4* av = (const float4*)(Actx + (size_t)row * DM);
    const float4* vv = (const float4*)(V    + (size_t)row * DM);
    float4*       ov = (float4*)(Out + (size_t)row * DM);
#pragma unroll
    for (int j = 0; j < 2; j++) {
        int d4 = lane * 2 + j;
        float4 a = av[d4], v = vv[d4];
        ov[d4] = make_float4(g*a.x + om*v.x, g*a.y + om*v.y,
                             g*a.z + om*v.z, g*a.w + om*v.w);
    }
}

// ---------------- launch ----------------
extern "C" void kernel_launch(void* const* d_in, const int* in_sizes, int n_in,
                              void* d_out, int out_size)
{
    const float* video = (const float*)d_in[0];
    const float* audio = (const float*)d_in[1];
    const float* Wv    = (const float*)d_in[2];
    const float* bv    = (const float*)d_in[3];
    const float* Wa    = (const float*)d_in[4];
    const float* ba    = (const float*)d_in[5];
    const float* theta = (const float*)d_in[6];
    const float* W1    = (const float*)d_in[7];
    const float* b1    = (const float*)d_in[8];
    const float* W2    = (const float*)d_in[9];
    const float* b2    = (const float*)d_in[10];
    float* out = (float*)d_out;

    float *pv, *pa, *pactx, *ph, *prnv;
    __half *pvf, *paf, *pxf, *pwv, *pwa, *pw1;
    cudaGetSymbolAddress((void**)&pv,    g_v);
    cudaGetSymbolAddress((void**)&pa,    g_a);
    cudaGetSymbolAddress((void**)&pactx, g_actx);
    cudaGetSymbolAddress((void**)&ph,    g_h);
    cudaGetSymbolAddress((void**)&prnv,  g_rnv);
    cudaGetSymbolAddress((void**)&pvf,   g_vf);
    cudaGetSymbolAddress((void**)&paf,   g_af);
    cudaGetSymbolAddress((void**)&pxf,   g_xf);
    cudaGetSymbolAddress((void**)&pwv,   g_wv);
    cudaGetSymbolAddress((void**)&pwa,   g_wa);
    cudaGetSymbolAddress((void**)&pw1,   g_w1);

    cudaFuncSetAttribute(tc_gemm<false>, cudaFuncAttributeMaxDynamicSharedMemorySize, SMEM_TOTAL_GEMM);
    cudaFuncSetAttribute(tc_gemm<true>,  cudaFuncAttributeMaxDynamicSharedMemorySize, SMEM_TOTAL_GEMM);

    cvt_kernel<<<(MROWS*VDIM/4 + 255)/256, 256>>>(video, pvf, MROWS*VDIM/4);             // 1
    wcvt_kernel<<<(VDIM*DM + 255)/256, 256>>>(Wv, pwv, VDIM, DM);                        // 2
    wcvt_kernel<<<(ADIM*DM + 255)/256, 256>>>(Wa, pwa, ADIM, DM);                        // 3
    tc_gemm<false><<<dim3(DM/128, MROWS/128), 256, SMEM_TOTAL_GEMM>>>(                   // 4
        pvf, pwv, bv, pv, VDIM, DM);
    cvt_kernel<<<(MROWS*ADIM/4 + 255)/256, 256>>>(audio, paf, MROWS*ADIM/4);             // 5
    tc_gemm<false><<<dim3(DM/128, MROWS/128), 256, SMEM_TOTAL_GEMM>>>(                   // 6
        paf, pwa, ba, pa, ADIM, DM);
    wcvt_kernel<<<(XDIM*HID + 255)/256, 256>>>(W1, pw1, XDIM, HID);                      // 7

    ln_kernel<<<MROWS/8, 256>>>(pv, prnv);                                               // 8
    ln_kernel<<<MROWS/8, 256>>>(pa, (float*)nullptr);                                    // 9
    shiftbox_kernel<<<(MROWS*64)/256, 256>>>(pa, pactx, theta);                          // 10
    buildx_kernel<<<MROWS/8, 256>>>(pactx, pv, prnv, pxf);                               // 11
    tc_gemm<true><<<dim3(HID/128, MROWS/128), 256, SMEM_TOTAL_GEMM>>>(                   // 12
        pxf, pw1, b1, ph, XDIM, HID);
    final_kernel<<<MROWS/8, 256>>>(ph, pactx, pv, W2, b2, out);                          // 13
}

// round 14
// speedup vs baseline: 2.3275x; 1.0632x over previous
#include <cuda_runtime.h>
#include <cuda_fp16.h>
#include <math.h>
#include <stdint.h>

// ---------------- problem constants ----------------
#define BB 8
#define TT 2048
#define VDIM 1024
#define ADIM 768
#define DM 256
#define HID 1024
#define MROWS (BB*TT)     /* 16384 */
#define XDIM (3*DM)       /* 768 */

// ---------------- device scratch ----------------
__device__ __align__(16) float g_v[MROWS*DM];      // LN'd video proj
__device__ __align__(16) float g_a[MROWS*DM];      // LN'd audio proj
__device__ __align__(16) float g_actx[MROWS*DM];
__device__ __align__(16) float g_h[MROWS*HID];
__device__ float g_rnv[MROWS];
// fp16 operands
__device__ __align__(16) __half g_vf[MROWS*VDIM];
__device__ __align__(16) __half g_af[MROWS*ADIM];
__device__ __align__(16) __half g_xf[MROWS*XDIM];
// transposed fp16 weights [N,K]
__device__ __align__(16) __half g_wv[DM*VDIM];
__device__ __align__(16) __half g_wa[DM*ADIM];
__device__ __align__(16) __half g_w1[HID*XDIM];

// ---------------- helpers ----------------
__device__ __forceinline__ float warp_sum(float v) {
#pragma unroll
    for (int o = 16; o > 0; o >>= 1) v += __shfl_xor_sync(0xffffffffu, v, o);
    return v;
}
__device__ __forceinline__ float gelu_exact(float x) {
    return 0.5f * x * (1.0f + erff(x * 0.70710678118654752f));
}
__device__ __forceinline__ void cp_async16(uint32_t dst, const void* src) {
    asm volatile("cp.async.cg.shared.global [%0], [%1], 16;" :: "r"(dst), "l"(src));
}
__device__ __forceinline__ void cp_commit() {
    asm volatile("cp.async.commit_group;" ::: "memory");
}
template<int N> __device__ __forceinline__ void cp_wait() {
    asm volatile("cp.async.wait_group %0;" :: "n"(N) : "memory");
}
__device__ __forceinline__ uint32_t smem_u32(const void* p) {
    uint32_t a;
    asm("{ .reg .u64 t; cvta.to.shared.u64 t, %1; cvt.u32.u64 %0, t; }" : "=r"(a) : "l"(p));
    return a;
}
__device__ __forceinline__ void mma_f16(float* c, const uint32_t* a, const uint32_t* b) {
    asm volatile(
        "mma.sync.aligned.m16n8k16.row.col.f32.f16.f16.f32 "
        "{%0,%1,%2,%3}, {%4,%5,%6,%7}, {%8,%9}, {%0,%1,%2,%3};"
        : "+f"(c[0]), "+f"(c[1]), "+f"(c[2]), "+f"(c[3])
        : "r"(a[0]), "r"(a[1]), "r"(a[2]), "r"(a[3]), "r"(b[0]), "r"(b[1]));
}
__device__ __forceinline__ void ldsm_x4(uint32_t* r, uint32_t addr) {
    asm volatile("ldmatrix.sync.aligned.m8n8.x4.shared.b16 {%0,%1,%2,%3}, [%4];"
        : "=r"(r[0]), "=r"(r[1]), "=r"(r[2]), "=r"(r[3]) : "r"(addr));
}

#define SROWB 144                      /* smem row stride bytes: 128 data + 16 pad */

// ================= projection GEMM with fused LayerNorm =================
// C[M,256] = LN_row(A[M,K] @ B^T + bias); optional rn[row] = 1/||LN row||.
// Tile 128x256, 512 threads = 16 warps (4 M x 4 N), warp tile 32x64, BK=64.
#define A_BYTES_LN (128*SROWB)             /* 18432 */
#define B_BYTES_LN (256*SROWB)             /* 36864 */
#define STAGE_LN   (A_BYTES_LN+B_BYTES_LN) /* 55296 */
#define SMEM_LN    (3*STAGE_LN)            /* 165888 */

__global__ void __launch_bounds__(512, 1) tc_gemm_ln(
    const __half* __restrict__ A, const __half* __restrict__ B,
    const float* __restrict__ bias, float* __restrict__ C,
    float* __restrict__ rn, int K)
{
    extern __shared__ __half smem[];
    uint32_t sbase = smem_u32(smem);
    const int tid    = threadIdx.x;
    const int wid    = tid >> 5;
    const int lane   = tid & 31;
    const int warp_m = wid >> 2;          // 0..3
    const int warp_n = wid & 3;           // 0..3
    const int lr     = lane >> 2;         // 0..7
    const int lc     = lane & 3;          // 0..3
    const int lr8    = lane & 7;
    const int lg     = lane >> 3;
    const int row0   = blockIdx.x * 128;

    const __half* Ap = A + (size_t)row0 * K;
    const int nk = K >> 6;

    uint32_t aoff[2], boff[4];
#pragma unroll
    for (int im = 0; im < 2; im++)
        aoff[im] = (uint32_t)((warp_m*32 + im*16 + (lg & 1)*8 + lr8) * SROWB + ((lg >> 1)*8) * 2);
#pragma unroll
    for (int ip = 0; ip < 4; ip++)
        boff[ip] = (uint32_t)((warp_n*64 + ip*16 + (lg >> 1)*8 + lr8) * SROWB + ((lg & 1)*8) * 2);

    auto load_stage = [&](int kt) {
        uint32_t sb = sbase + (uint32_t)(kt % 3) * STAGE_LN;
        int koff = kt * 64;
#pragma unroll
        for (int i = 0; i < 2; i++) {             // A: 1024 chunks
            int id = tid + i * 512;
            int r  = id >> 3, c = id & 7;
            cp_async16(sb + (uint32_t)(r * SROWB + c * 16),
                       Ap + (size_t)r * K + koff + c * 8);
        }
#pragma unroll
        for (int i = 0; i < 4; i++) {             // B: 2048 chunks
            int id = tid + i * 512;
            int r  = id >> 3, c = id & 7;
            cp_async16(sb + A_BYTES_LN + (uint32_t)(r * SROWB + c * 16),
                       B + (size_t)r * K + koff + c * 8);
        }
        cp_commit();
    };

    float acc[2][8][4];
#pragma unroll
    for (int im = 0; im < 2; im++)
#pragma unroll
        for (int in = 0; in < 8; in++)
#pragma unroll
            for (int j = 0; j < 4; j++) acc[im][in][j] = 0.f;

    load_stage(0);
    load_stage(1);

    for (int k = 0; k < nk; k++) {
        if (k == nk - 1) cp_wait<0>();
        else             cp_wait<1>();
        __syncthreads();
        if (k + 2 < nk) load_stage(k + 2);

        uint32_t sA = sbase + (uint32_t)(k % 3) * STAGE_LN;
        uint32_t sB = sA + A_BYTES_LN;

#pragma unroll
        for (int kk = 0; kk < 4; kk++) {
            uint32_t kb = (uint32_t)(kk * 32);
            uint32_t a[2][4], b[8][2];
#pragma unroll
            for (int im = 0; im < 2; im++)
                ldsm_x4(a[im], sA + aoff[im] + kb);
#pragma unroll
            for (int ip = 0; ip < 4; ip++) {
                uint32_t t[4];
                ldsm_x4(t, sB + boff[ip] + kb);
                b[2*ip][0] = t[0]; b[2*ip][1] = t[1];
                b[2*ip+1][0] = t[2]; b[2*ip+1][1] = t[3];
            }
#pragma unroll
            for (int im = 0; im < 2; im++)
#pragma unroll
                for (int in = 0; in < 8; in++)
                    mma_f16(acc[im][in], a[im], b[in]);
        }
    }

    // ---- LN epilogue ----
    // add bias
    float bcol[8][2];
#pragma unroll
    for (int in = 0; in < 8; in++) {
        int c = warp_n * 64 + in * 8 + lc * 2;
        bcol[in][0] = bias[c]; bcol[in][1] = bias[c + 1];
    }
#pragma unroll
    for (int im = 0; im < 2; im++)
#pragma unroll
        for (int in = 0; in < 8; in++) {
            acc[im][in][0] += bcol[in][0]; acc[im][in][1] += bcol[in][1];
            acc[im][in][2] += bcol[in][0]; acc[im][in][3] += bcol[in][1];
        }

    __syncthreads();   // all smem stage reads done; reuse smem for partials
    float* part = (float*)smem;   // [128 rows][4 warp_n][2]

    // per-thread partial sums for its 4 rows (im x h)
#pragma unroll
    for (int im = 0; im < 2; im++)
#pragma unroll
        for (int h = 0; h < 2; h++) {
            float s = 0.f, s2 = 0.f;
#pragma unroll
            for (int in = 0; in < 8; in++) {
                float v0 = acc[im][in][2*h], v1 = acc[im][in][2*h + 1];
                s += v0 + v1; s2 += v0*v0 + v1*v1;
            }
            s  += __shfl_xor_sync(0xffffffffu, s, 1);
            s  += __shfl_xor_sync(0xffffffffu, s, 2);
            s2 += __shfl_xor_sync(0xffffffffu, s2, 1);
            s2 += __shfl_xor_sync(0xffffffffu, s2, 2);
            if (lc == 0) {
                int r = warp_m*32 + im*16 + h*8 + lr;
                part[r*8 + warp_n*2]     = s;
                part[r*8 + warp_n*2 + 1] = s2;
            }
        }
    __syncthreads();

#pragma unroll
    for (int im = 0; im < 2; im++)
#pragma unroll
        for (int h = 0; h < 2; h++) {
            int r = warp_m*32 + im*16 + h*8 + lr;
            float S1 = part[r*8] + part[r*8+2] + part[r*8+4] + part[r*8+6];
            float S2 = part[r*8+1] + part[r*8+3] + part[r*8+5] + part[r*8+7];
            float mu = S1 * (1.0f / DM);
            float q  = fmaxf(S2 - S1 * mu, 0.f);          // Σ(x-mu)^2
            float inv = 1.0f / sqrtf(q * (1.0f / DM) + 1e-5f);
            if (rn && warp_n == 0 && lc == 0)
                rn[row0 + r] = 1.0f / fmaxf(sqrtf(q) * inv, 1e-8f);
#pragma unroll
            for (int in = 0; in < 8; in++) {
                float2 o;
                o.x = (acc[im][in][2*h]     - mu) * inv;
                o.y = (acc[im][in][2*h + 1] - mu) * inv;
                int c = warp_n * 64 + in * 8 + lc * 2;
                *(float2*)&C[(size_t)(row0 + r) * DM + c] = o;
            }
        }
}

// ================= MLP GEMM with gelu epilogue (BK=64, 2 CTAs/SM) =================
#define OP_BYTES (128*SROWB)           /* 18432 B per operand */
#define STAGE_BYTES (2*OP_BYTES)       /* 36864 B */
#define SMEM_GELU (3*STAGE_BYTES)      /* 110592 B */

__global__ void __launch_bounds__(256, 2) tc_gemm_gelu(
    const __half* __restrict__ A, const __half* __restrict__ B,
    const float* __restrict__ bias, float* __restrict__ C, int K, int N)
{
    extern __shared__ __half smem[];
    uint32_t sbase = smem_u32(smem);
    const int tid    = threadIdx.x;
    const int wid    = tid >> 5;
    const int lane   = tid & 31;
    const int warp_m = wid >> 1;
    const int warp_n = wid & 1;
    const int lr     = lane >> 2;
    const int lc     = lane & 3;
    const int lr8    = lane & 7;
    const int lg     = lane >> 3;
    const int row0   = blockIdx.y * 128;
    const int col0   = blockIdx.x * 128;

    const __half* Ap = A + (size_t)row0 * K;
    const __half* Bp = B + (size_t)col0 * K;
    const int nk = K >> 6;

    uint32_t aoff[2], boff[4];
#pragma unroll
    for (int im = 0; im < 2; im++)
        aoff[im] = (uint32_t)((warp_m*32 + im*16 + (lg & 1)*8 + lr8) * SROWB + ((lg >> 1)*8) * 2);
#pragma unroll
    for (int ip = 0; ip < 4; ip++)
        boff[ip] = (uint32_t)((warp_n*64 + ip*16 + (lg >> 1)*8 + lr8) * SROWB + ((lg & 1)*8) * 2);

    auto load_stage = [&](int kt) {
        uint32_t sb = sbase + (uint32_t)(kt % 3) * STAGE_BYTES;
        int koff = kt * 64;
#pragma unroll
        for (int i = 0; i < 4; i++) {
            int id = tid + i * 256;
            int r  = id >> 3, c = id & 7;
            uint32_t soff = (uint32_t)(r * SROWB + c * 16);
            size_t   goff = (size_t)r * K + koff + c * 8;
            cp_async16(sb +            soff, Ap + goff);
            cp_async16(sb + OP_BYTES + soff, Bp + goff);
        }
        cp_commit();
    };

    float acc[2][8][4];
#pragma unroll
    for (int im = 0; im < 2; im++)
#pragma unroll
        for (int in = 0; in < 8; in++)
#pragma unroll
            for (int j = 0; j < 4; j++) acc[im][in][j] = 0.f;

    load_stage(0);
    load_stage(1);

    for (int k = 0; k < nk; k++) {
        if (k == nk - 1) cp_wait<0>();
        else             cp_wait<1>();
        __syncthreads();
        if (k + 2 < nk) load_stage(k + 2);

        uint32_t sA = sbase + (uint32_t)(k % 3) * STAGE_BYTES;
        uint32_t sB = sA + OP_BYTES;

#pragma unroll
        for (int kk = 0; kk < 4; kk++) {
            uint32_t kb = (uint32_t)(kk * 32);
            uint32_t a[2][4], b[8][2];
#pragma unroll
            for (int im = 0; im < 2; im++)
                ldsm_x4(a[im], sA + aoff[im] + kb);
#pragma unroll
            for (int ip = 0; ip < 4; ip++) {
                uint32_t t[4];
                ldsm_x4(t, sB + boff[ip] + kb);
                b[2*ip][0] = t[0]; b[2*ip][1] = t[1];
                b[2*ip+1][0] = t[2]; b[2*ip+1][1] = t[3];
            }
#pragma unroll
            for (int im = 0; im < 2; im++)
#pragma unroll
                for (int in = 0; in < 8; in++)
                    mma_f16(acc[im][in], a[im], b[in]);
        }
    }

#pragma unroll
    for (int im = 0; im < 2; im++) {
        int r0 = row0 + warp_m * 32 + im * 16 + lr;
#pragma unroll
        for (int in = 0; in < 8; in++) {
            int c = col0 + warp_n * 64 + in * 8 + lc * 2;
            float b0 = bias[c], b1 = bias[c + 1];
            float2 v0, v1;
            v0.x = gelu_exact(acc[im][in][0] + b0); v0.y = gelu_exact(acc[im][in][1] + b1);
            v1.x = gelu_exact(acc[im][in][2] + b0); v1.y = gelu_exact(acc[im][in][3] + b1);
            *(float2*)&C[(size_t)(r0    ) * N + c] = v0;
            *(float2*)&C[(size_t)(r0 + 8) * N + c] = v1;
        }
    }
}

// ---------------- pre-pass: convert fp32 -> fp16 ----------------
__global__ void __launch_bounds__(256) cvt_kernel(
    const float* __restrict__ X, __half* __restrict__ H, int n4)
{
    int i = blockIdx.x * 256 + threadIdx.x;
    if (i >= n4) return;
    float4 x = ((const float4*)X)[i];
    __half h[4] = {__float2half(x.x), __float2half(x.y),
                   __float2half(x.z), __float2half(x.w)};
    ((uint2*)H)[i] = *(uint2*)h;
}

// ---------------- pre-pass: transpose + convert weights [K,N] -> [N,K] fp16 ----------------
__global__ void __launch_bounds__(256) wcvt_kernel(
    const float* __restrict__ W, __half* __restrict__ Ht, int K, int N)
{
    int i = blockIdx.x * 256 + threadIdx.x;
    if (i >= K * N) return;
    int k = i / N, n = i % N;
    Ht[(size_t)n * K + k] = __float2half(W[i]);
}

// ---- fused: fractional shift + box avg + rnorm + build x (warp per row) ----
__global__ void __launch_bounds__(256) shiftbuildx_kernel(
    const float* __restrict__ A, const float* __restrict__ V,
    const float* __restrict__ rnv, float* __restrict__ Actx,
    __half* __restrict__ XH, const float* __restrict__ theta)
{
    int row  = blockIdx.x * 8 + (threadIdx.x >> 5);
    int lane = threadIdx.x & 31;
    int b = row / TT, t = row % TT;

    float th    = fminf(fmaxf(theta[0], -12.0f), 12.0f);
    float delta = 2.0f + 4.0f / (1.0f + expf(-th));
    float dl    = fminf(fmaxf(delta, 0.0f), (float)(TT - 1));
    float nf    = floorf(dl);
    float alpha = dl - nf;
    int   ni    = (int)nf;

    float center = fminf(fmaxf((float)t + delta, 0.0f), (float)t);
    int lo = max(0, (int)ceilf(center - 5.0f));
    int hi = min(t, (int)floorf(center + 5.0f));

    const float* base = A + (size_t)b * TT * DM + lane * 8;
    float acc[8] = {0,0,0,0,0,0,0,0};
    float w0 = 1.0f - alpha, w1 = alpha;
    for (int tau = lo; tau <= hi; tau++) {
        int i0 = min(max(tau - ni, 0), TT - 1);
        int i1 = min(i0 + 1, TT - 1);
        const float* p0 = base + (size_t)i0 * DM;
        const float* p1 = base + (size_t)i1 * DM;
        float4 x0a = *(const float4*)p0, x0b = *(const float4*)(p0 + 4);
        float4 x1a = *(const float4*)p1, x1b = *(const float4*)(p1 + 4);
        acc[0] += w0*x0a.x + w1*x1a.x; acc[1] += w0*x0a.y + w1*x1a.y;
        acc[2] += w0*x0a.z + w1*x1a.z; acc[3] += w0*x0a.w + w1*x1a.w;
        acc[4] += w0*x0b.x + w1*x1b.x; acc[5] += w0*x0b.y + w1*x1b.y;
        acc[6] += w0*x0b.z + w1*x1b.z; acc[7] += w0*x0b.w + w1*x1b.w;
    }
    float scale = 1.0f / fmaxf((float)(hi - lo + 1), 1e-8f);
#pragma unroll
    for (int i = 0; i < 8; i++) acc[i] *= scale;

    // write actx
    float* ao = Actx + (size_t)row * DM + lane * 8;
    *(float4*)ao       = *(float4*)&acc[0];
    *(float4*)(ao + 4) = *(float4*)&acc[4];

    // rnorm of actx
    float q = 0.f;
#pragma unroll
    for (int i = 0; i < 8; i++) q += acc[i] * acc[i];
    q = warp_sum(q);
    float ra = 1.0f / fmaxf(sqrtf(q), 1e-8f);
    float rv = rnv[row];

    const float* vr = V + (size_t)row * DM + lane * 8;
    float v[8];
    *(float4*)&v[0] = *(const float4*)vr;
    *(float4*)&v[4] = *(const float4*)(vr + 4);

    __half an[8], vn[8], pr[8];
#pragma unroll
    for (int i = 0; i < 8; i++) {
        float anf = acc[i] * ra, vnf = v[i] * rv;
        an[i] = __float2half(anf);
        vn[i] = __float2half(vnf);
        pr[i] = __float2half(anf * vnf);
    }
    size_t xb = (size_t)row * XDIM + lane * 8;
    *(uint4*)&XH[xb]        = *(uint4*)an;
    *(uint4*)&XH[xb + DM]   = *(uint4*)vn;
    *(uint4*)&XH[xb + 2*DM] = *(uint4*)pr;
}

// ---------------- final: logit = h@W2+b2, gate, blend (warp per row) ----------------
__global__ void __launch_bounds__(256) final_kernel(
    const float* __restrict__ H, const float* __restrict__ Actx,
    const float* __restrict__ V, const float* __restrict__ W2,
    const float* __restrict__ b2, float* __restrict__ Out)
{
    int row  = blockIdx.x * 8 + (threadIdx.x >> 5);
    int lane = threadIdx.x & 31;
    const float* hr = H + (size_t)row * HID;
    float s = 0.f;
#pragma unroll
    for (int i = 0; i < 32; i++) {
        int k = i * 32 + lane;
        s = fmaf(hr[k], W2[k], s);
    }
    s = warp_sum(s);
    float logit = fminf(fmaxf(s + b2[0], -12.0f), 12.0f);
    float g = 1.0f / (1.0f + expf(-logit));
    g = fminf(fmaxf(g, 0.05f), 0.95f);
    float om = 1.0f - g;

    const float4* av = (const float4*)(Actx + (size_t)row * DM);
    const float4* vv = (const float4*)(V    + (size_t)row * DM);
    float4*       ov = (float4*)(Out + (size_t)row * DM);
#pragma unroll
    for (int j = 0; j < 2; j++) {
        int d4 = lane * 2 + j;
        float4 a = av[d4], v = vv[d4];
        ov[d4] = make_float4(g*a.x + om*v.x, g*a.y + om*v.y,
                             g*a.z + om*v.z, g*a.w + om*v.w);
    }
}

// ---------------- launch ----------------
extern "C" void kernel_launch(void* const* d_in, const int* in_sizes, int n_in,
                              void* d_out, int out_size)
{
    const float* video = (const float*)d_in[0];
    const float* audio = (const float*)d_in[1];
    const float* Wv    = (const float*)d_in[2];
    const float* bv    = (const float*)d_in[3];
    const float* Wa    = (const float*)d_in[4];
    const float* ba    = (const float*)d_in[5];
    const float* theta = (const float*)d_in[6];
    const float* W1    = (const float*)d_in[7];
    const float* b1    = (const float*)d_in[8];
    const float* W2    = (const float*)d_in[9];
    const float* b2    = (const float*)d_in[10];
    float* out = (float*)d_out;

    float *pv, *pa, *pactx, *ph, *prnv;
    __half *pvf, *paf, *pxf, *pwv, *pwa, *pw1;
    cudaGetSymbolAddress((void**)&pv,    g_v);
    cudaGetSymbolAddress((void**)&pa,    g_a);
    cudaGetSymbolAddress((void**)&pactx, g_actx);
    cudaGetSymbolAddress((void**)&ph,    g_h);
    cudaGetSymbolAddress((void**)&prnv,  g_rnv);
    cudaGetSymbolAddress((void**)&pvf,   g_vf);
    cudaGetSymbolAddress((void**)&paf,   g_af);
    cudaGetSymbolAddress((void**)&pxf,   g_xf);
    cudaGetSymbolAddress((void**)&pwv,   g_wv);
    cudaGetSymbolAddress((void**)&pwa,   g_wa);
    cudaGetSymbolAddress((void**)&pw1,   g_w1);

    cudaFuncSetAttribute(tc_gemm_ln,   cudaFuncAttributeMaxDynamicSharedMemorySize, SMEM_LN);
    cudaFuncSetAttribute(tc_gemm_gelu, cudaFuncAttributeMaxDynamicSharedMemorySize, SMEM_GELU);

    cvt_kernel<<<(MROWS*VDIM/4 + 255)/256, 256>>>(video, pvf, MROWS*VDIM/4);             // 1
    wcvt_kernel<<<(VDIM*DM + 255)/256, 256>>>(Wv, pwv, VDIM, DM);                        // 2
    wcvt_kernel<<<(ADIM*DM + 255)/256, 256>>>(Wa, pwa, ADIM, DM);                        // 3
    tc_gemm_ln<<<MROWS/128, 512, SMEM_LN>>>(pvf, pwv, bv, pv, prnv, VDIM);               // 4
    cvt_kernel<<<(MROWS*ADIM/4 + 255)/256, 256>>>(audio, paf, MROWS*ADIM/4);             // 5
    tc_gemm_ln<<<MROWS/128, 512, SMEM_LN>>>(paf, pwa, ba, pa, (float*)nullptr, ADIM);    // 6
    wcvt_kernel<<<(XDIM*HID + 255)/256, 256>>>(W1, pw1, XDIM, HID);                      // 7
    shiftbuildx_kernel<<<MROWS/8, 256>>>(pa, pv, prnv, pactx, pxf, theta);               // 8
    tc_gemm_gelu<<<dim3(HID/128, MROWS/128), 256, SMEM_GELU>>>(                          // 9
        pxf, pw1, b1, ph, XDIM, HID);
    final_kernel<<<MROWS/8, 256>>>(ph, pactx, pv, W2, b2, out);                          // 10
}

// round 15
// speedup vs baseline: 2.4499x; 1.0526x over previous
#include <cuda_runtime.h>
#include <cuda_fp16.h>
#include <math.h>
#include <stdint.h>

// ---------------- problem constants ----------------
#define BB 8
#define TT 2048
#define VDIM 1024
#define ADIM 768
#define DM 256
#define HID 1024
#define MROWS (BB*TT)     /* 16384 */
#define XDIM (3*DM)       /* 768 */

// ---------------- device scratch ----------------
__device__ __align__(16) float g_v[MROWS*DM];      // LN'd video proj
__device__ __align__(16) float g_a[MROWS*DM];      // LN'd audio proj
__device__ __align__(16) float g_actx[MROWS*DM];
__device__ float g_rnv[MROWS];
__device__ float g_logits[MROWS];
// fp16 operands
__device__ __align__(16) __half g_vf[MROWS*VDIM];
__device__ __align__(16) __half g_af[MROWS*ADIM];
__device__ __align__(16) __half g_xf[MROWS*XDIM];
// transposed fp16 weights [N,K]
__device__ __align__(16) __half g_wv[DM*VDIM];
__device__ __align__(16) __half g_wa[DM*ADIM];
__device__ __align__(16) __half g_w1[HID*XDIM];

// ---------------- helpers ----------------
__device__ __forceinline__ float warp_sum(float v) {
#pragma unroll
    for (int o = 16; o > 0; o >>= 1) v += __shfl_xor_sync(0xffffffffu, v, o);
    return v;
}
__device__ __forceinline__ float gelu_exact(float x) {
    return 0.5f * x * (1.0f + erff(x * 0.70710678118654752f));
}
__device__ __forceinline__ void cp_async16(uint32_t dst, const void* src) {
    asm volatile("cp.async.cg.shared.global [%0], [%1], 16;" :: "r"(dst), "l"(src));
}
__device__ __forceinline__ void cp_commit() {
    asm volatile("cp.async.commit_group;" ::: "memory");
}
template<int N> __device__ __forceinline__ void cp_wait() {
    asm volatile("cp.async.wait_group %0;" :: "n"(N) : "memory");
}
__device__ __forceinline__ uint32_t smem_u32(const void* p) {
    uint32_t a;
    asm("{ .reg .u64 t; cvta.to.shared.u64 t, %1; cvt.u32.u64 %0, t; }" : "=r"(a) : "l"(p));
    return a;
}
__device__ __forceinline__ void mma_f16(float* c, const uint32_t* a, const uint32_t* b) {
    asm volatile(
        "mma.sync.aligned.m16n8k16.row.col.f32.f16.f16.f32 "
        "{%0,%1,%2,%3}, {%4,%5,%6,%7}, {%8,%9}, {%0,%1,%2,%3};"
        : "+f"(c[0]), "+f"(c[1]), "+f"(c[2]), "+f"(c[3])
        : "r"(a[0]), "r"(a[1]), "r"(a[2]), "r"(a[3]), "r"(b[0]), "r"(b[1]));
}
__device__ __forceinline__ void ldsm_x4(uint32_t* r, uint32_t addr) {
    asm volatile("ldmatrix.sync.aligned.m8n8.x4.shared.b16 {%0,%1,%2,%3}, [%4];"
        : "=r"(r[0]), "=r"(r[1]), "=r"(r[2]), "=r"(r[3]) : "r"(addr));
}

#define SROWB 144                      /* smem row stride bytes: 128 data + 16 pad */

// ================= projection GEMM with fused LayerNorm =================
// C[M,256] = LN_row(A[M,K] @ B^T + bias); optional rn[row] = 1/||LN row||.
// Tile 128x256, 512 threads = 16 warps (4 M x 4 N), warp tile 32x64, BK=64.
#define A_BYTES_LN (128*SROWB)             /* 18432 */
#define B_BYTES_LN (256*SROWB)             /* 36864 */
#define STAGE_LN   (A_BYTES_LN+B_BYTES_LN) /* 55296 */
#define SMEM_LN    (3*STAGE_LN)            /* 165888 */

__global__ void __launch_bounds__(512, 1) tc_gemm_ln(
    const __half* __restrict__ A, const __half* __restrict__ B,
    const float* __restrict__ bias, float* __restrict__ C,
    float* __restrict__ rn, int K)
{
    extern __shared__ __half smem[];
    uint32_t sbase = smem_u32(smem);
    const int tid    = threadIdx.x;
    const int wid    = tid >> 5;
    const int lane   = tid & 31;
    const int warp_m = wid >> 2;          // 0..3
    const int warp_n = wid & 3;           // 0..3
    const int lr     = lane >> 2;         // 0..7
    const int lc     = lane & 3;          // 0..3
    const int lr8    = lane & 7;
    const int lg     = lane >> 3;
    const int row0   = blockIdx.x * 128;

    const __half* Ap = A + (size_t)row0 * K;
    const int nk = K >> 6;

    uint32_t aoff[2], boff[4];
#pragma unroll
    for (int im = 0; im < 2; im++)
        aoff[im] = (uint32_t)((warp_m*32 + im*16 + (lg & 1)*8 + lr8) * SROWB + ((lg >> 1)*8) * 2);
#pragma unroll
    for (int ip = 0; ip < 4; ip++)
        boff[ip] = (uint32_t)((warp_n*64 + ip*16 + (lg >> 1)*8 + lr8) * SROWB + ((lg & 1)*8) * 2);

    auto load_stage = [&](int kt) {
        uint32_t sb = sbase + (uint32_t)(kt % 3) * STAGE_LN;
        int koff = kt * 64;
#pragma unroll
        for (int i = 0; i < 2; i++) {             // A: 1024 chunks
            int id = tid + i * 512;
            int r  = id >> 3, c = id & 7;
            cp_async16(sb + (uint32_t)(r * SROWB + c * 16),
                       Ap + (size_t)r * K + koff + c * 8);
        }
#pragma unroll
        for (int i = 0; i < 4; i++) {             // B: 2048 chunks
            int id = tid + i * 512;
            int r  = id >> 3, c = id & 7;
            cp_async16(sb + A_BYTES_LN + (uint32_t)(r * SROWB + c * 16),
                       B + (size_t)r * K + koff + c * 8);
        }
        cp_commit();
    };

    float acc[2][8][4];
#pragma unroll
    for (int im = 0; im < 2; im++)
#pragma unroll
        for (int in = 0; in < 8; in++)
#pragma unroll
            for (int j = 0; j < 4; j++) acc[im][in][j] = 0.f;

    load_stage(0);
    load_stage(1);

    for (int k = 0; k < nk; k++) {
        if (k == nk - 1) cp_wait<0>();
        else             cp_wait<1>();
        __syncthreads();
        if (k + 2 < nk) load_stage(k + 2);

        uint32_t sA = sbase + (uint32_t)(k % 3) * STAGE_LN;
        uint32_t sB = sA + A_BYTES_LN;

#pragma unroll
        for (int kk = 0; kk < 4; kk++) {
            uint32_t kb = (uint32_t)(kk * 32);
            uint32_t a[2][4], b[8][2];
#pragma unroll
            for (int im = 0; im < 2; im++)
                ldsm_x4(a[im], sA + aoff[im] + kb);
#pragma unroll
            for (int ip = 0; ip < 4; ip++) {
                uint32_t t[4];
                ldsm_x4(t, sB + boff[ip] + kb);
                b[2*ip][0] = t[0]; b[2*ip][1] = t[1];
                b[2*ip+1][0] = t[2]; b[2*ip+1][1] = t[3];
            }
#pragma unroll
            for (int im = 0; im < 2; im++)
#pragma unroll
                for (int in = 0; in < 8; in++)
                    mma_f16(acc[im][in], a[im], b[in]);
        }
    }

    // ---- LN epilogue ----
    float bcol[8][2];
#pragma unroll
    for (int in = 0; in < 8; in++) {
        int c = warp_n * 64 + in * 8 + lc * 2;
        bcol[in][0] = bias[c]; bcol[in][1] = bias[c + 1];
    }
#pragma unroll
    for (int im = 0; im < 2; im++)
#pragma unroll
        for (int in = 0; in < 8; in++) {
            acc[im][in][0] += bcol[in][0]; acc[im][in][1] += bcol[in][1];
            acc[im][in][2] += bcol[in][0]; acc[im][in][3] += bcol[in][1];
        }

    __syncthreads();   // all smem stage reads done; reuse smem for partials
    float* part = (float*)smem;   // [128 rows][4 warp_n][2]

#pragma unroll
    for (int im = 0; im < 2; im++)
#pragma unroll
        for (int h = 0; h < 2; h++) {
            float s = 0.f, s2 = 0.f;
#pragma unroll
            for (int in = 0; in < 8; in++) {
                float v0 = acc[im][in][2*h], v1 = acc[im][in][2*h + 1];
                s += v0 + v1; s2 += v0*v0 + v1*v1;
            }
            s  += __shfl_xor_sync(0xffffffffu, s, 1);
            s  += __shfl_xor_sync(0xffffffffu, s, 2);
            s2 += __shfl_xor_sync(0xffffffffu, s2, 1);
            s2 += __shfl_xor_sync(0xffffffffu, s2, 2);
            if (lc == 0) {
                int r = warp_m*32 + im*16 + h*8 + lr;
                part[r*8 + warp_n*2]     = s;
                part[r*8 + warp_n*2 + 1] = s2;
            }
        }
    __syncthreads();

#pragma unroll
    for (int im = 0; im < 2; im++)
#pragma unroll
        for (int h = 0; h < 2; h++) {
            int r = warp_m*32 + im*16 + h*8 + lr;
            float S1 = part[r*8] + part[r*8+2] + part[r*8+4] + part[r*8+6];
            float S2 = part[r*8+1] + part[r*8+3] + part[r*8+5] + part[r*8+7];
            float mu = S1 * (1.0f / DM);
            float q  = fmaxf(S2 - S1 * mu, 0.f);          // Σ(x-mu)^2
            float inv = 1.0f / sqrtf(q * (1.0f / DM) + 1e-5f);
            if (rn && warp_n == 0 && lc == 0)
                rn[row0 + r] = 1.0f / fmaxf(sqrtf(q) * inv, 1e-8f);
#pragma unroll
            for (int in = 0; in < 8; in++) {
                float2 o;
                o.x = (acc[im][in][2*h]     - mu) * inv;
                o.y = (acc[im][in][2*h + 1] - mu) * inv;
                int c = warp_n * 64 + in * 8 + lc * 2;
                *(float2*)&C[(size_t)(row0 + r) * DM + c] = o;
            }
        }
}

// ====== MLP GEMM: gelu + fused h@W2 partial dot -> atomicAdd(logits) ======
// No hidden-state output at all.
#define OP_BYTES (128*SROWB)           /* 18432 B per operand */
#define STAGE_BYTES (2*OP_BYTES)       /* 36864 B */
#define SMEM_GELU (3*STAGE_BYTES)      /* 110592 B */

__global__ void __launch_bounds__(256, 2) tc_gemm_gelu_dot(
    const __half* __restrict__ A, const __half* __restrict__ B,
    const float* __restrict__ bias, const float* __restrict__ W2,
    float* __restrict__ logits, int K)
{
    extern __shared__ __half smem[];
    uint32_t sbase = smem_u32(smem);
    const int tid    = threadIdx.x;
    const int wid    = tid >> 5;
    const int lane   = tid & 31;
    const int warp_m = wid >> 1;
    const int warp_n = wid & 1;
    const int lr     = lane >> 2;
    const int lc     = lane & 3;
    const int lr8    = lane & 7;
    const int lg     = lane >> 3;
    const int row0   = blockIdx.y * 128;
    const int col0   = blockIdx.x * 128;

    const __half* Ap = A + (size_t)row0 * K;
    const __half* Bp = B + (size_t)col0 * K;
    const int nk = K >> 6;

    uint32_t aoff[2], boff[4];
#pragma unroll
    for (int im = 0; im < 2; im++)
        aoff[im] = (uint32_t)((warp_m*32 + im*16 + (lg & 1)*8 + lr8) * SROWB + ((lg >> 1)*8) * 2);
#pragma unroll
    for (int ip = 0; ip < 4; ip++)
        boff[ip] = (uint32_t)((warp_n*64 + ip*16 + (lg >> 1)*8 + lr8) * SROWB + ((lg & 1)*8) * 2);

    auto load_stage = [&](int kt) {
        uint32_t sb = sbase + (uint32_t)(kt % 3) * STAGE_BYTES;
        int koff = kt * 64;
#pragma unroll
        for (int i = 0; i < 4; i++) {
            int id = tid + i * 256;
            int r  = id >> 3, c = id & 7;
            uint32_t soff = (uint32_t)(r * SROWB + c * 16);
            size_t   goff = (size_t)r * K + koff + c * 8;
            cp_async16(sb +            soff, Ap + goff);
            cp_async16(sb + OP_BYTES + soff, Bp + goff);
        }
        cp_commit();
    };

    float acc[2][8][4];
#pragma unroll
    for (int im = 0; im < 2; im++)
#pragma unroll
        for (int in = 0; in < 8; in++)
#pragma unroll
            for (int j = 0; j < 4; j++) acc[im][in][j] = 0.f;

    load_stage(0);
    load_stage(1);

    for (int k = 0; k < nk; k++) {
        if (k == nk - 1) cp_wait<0>();
        else             cp_wait<1>();
        __syncthreads();
        if (k + 2 < nk) load_stage(k + 2);

        uint32_t sA = sbase + (uint32_t)(k % 3) * STAGE_BYTES;
        uint32_t sB = sA + OP_BYTES;

#pragma unroll
        for (int kk = 0; kk < 4; kk++) {
            uint32_t kb = (uint32_t)(kk * 32);
            uint32_t a[2][4], b[8][2];
#pragma unroll
            for (int im = 0; im < 2; im++)
                ldsm_x4(a[im], sA + aoff[im] + kb);
#pragma unroll
            for (int ip = 0; ip < 4; ip++) {
                uint32_t t[4];
                ldsm_x4(t, sB + boff[ip] + kb);
                b[2*ip][0] = t[0]; b[2*ip][1] = t[1];
                b[2*ip+1][0] = t[2]; b[2*ip+1][1] = t[3];
            }
#pragma unroll
            for (int im = 0; im < 2; im++)
#pragma unroll
                for (int in = 0; in < 8; in++)
                    mma_f16(acc[im][in], a[im], b[in]);
        }
    }

    // epilogue: gelu(acc+bias) dotted with W2 -> per-row partial -> atomicAdd
    float bc[8][2], w2[8][2];
#pragma unroll
    for (int in = 0; in < 8; in++) {
        int c = col0 + warp_n * 64 + in * 8 + lc * 2;
        bc[in][0] = bias[c];     bc[in][1] = bias[c + 1];
        w2[in][0] = __ldg(&W2[c]); w2[in][1] = __ldg(&W2[c + 1]);
    }
#pragma unroll
    for (int im = 0; im < 2; im++)
#pragma unroll
        for (int h = 0; h < 2; h++) {
            float s = 0.f;
#pragma unroll
            for (int in = 0; in < 8; in++) {
                float g0 = gelu_exact(acc[im][in][2*h]     + bc[in][0]);
                float g1 = gelu_exact(acc[im][in][2*h + 1] + bc[in][1]);
                s = fmaf(g0, w2[in][0], s);
                s = fmaf(g1, w2[in][1], s);
            }
            s += __shfl_xor_sync(0xffffffffu, s, 1);
            s += __shfl_xor_sync(0xffffffffu, s, 2);
            if (lc == 0) {
                int r = row0 + warp_m*32 + im*16 + h*8 + lr;
                atomicAdd(&logits[r], s);
            }
        }
}

// ---------------- zero logits ----------------
__global__ void __launch_bounds__(256) zero_kernel(float* __restrict__ p, int n)
{
    int i = blockIdx.x * 256 + threadIdx.x;
    if (i < n) p[i] = 0.f;
}

// ---------------- pre-pass: convert fp32 -> fp16 ----------------
__global__ void __launch_bounds__(256) cvt_kernel(
    const float* __restrict__ X, __half* __restrict__ H, int n4)
{
    int i = blockIdx.x * 256 + threadIdx.x;
    if (i >= n4) return;
    float4 x = ((const float4*)X)[i];
    __half h[4] = {__float2half(x.x), __float2half(x.y),
                   __float2half(x.z), __float2half(x.w)};
    ((uint2*)H)[i] = *(uint2*)h;
}

// ---------------- pre-pass: transpose + convert weights [K,N] -> [N,K] fp16 ----------------
__global__ void __launch_bounds__(256) wcvt_kernel(
    const float* __restrict__ W, __half* __restrict__ Ht, int K, int N)
{
    int i = blockIdx.x * 256 + threadIdx.x;
    if (i >= K * N) return;
    int k = i / N, n = i % N;
    Ht[(size_t)n * K + k] = __float2half(W[i]);
}

// ---- fused: fractional shift + box avg + rnorm + build x (warp per row) ----
__global__ void __launch_bounds__(256) shiftbuildx_kernel(
    const float* __restrict__ A, const float* __restrict__ V,
    const float* __restrict__ rnv, float* __restrict__ Actx,
    __half* __restrict__ XH, const float* __restrict__ theta)
{
    int row  = blockIdx.x * 8 + (threadIdx.x >> 5);
    int lane = threadIdx.x & 31;
    int b = row / TT, t = row % TT;

    float th    = fminf(fmaxf(theta[0], -12.0f), 12.0f);
    float delta = 2.0f + 4.0f / (1.0f + expf(-th));
    float dl    = fminf(fmaxf(delta, 0.0f), (float)(TT - 1));
    float nf    = floorf(dl);
    float alpha = dl - nf;
    int   ni    = (int)nf;

    float center = fminf(fmaxf((float)t + delta, 0.0f), (float)t);
    int lo = max(0, (int)ceilf(center - 5.0f));
    int hi = min(t, (int)floorf(center + 5.0f));

    const float* base = A + (size_t)b * TT * DM + lane * 8;
    float acc[8] = {0,0,0,0,0,0,0,0};
    float w0 = 1.0f - alpha, w1 = alpha;
    for (int tau = lo; tau <= hi; tau++) {
        int i0 = min(max(tau - ni, 0), TT - 1);
        int i1 = min(i0 + 1, TT - 1);
        const float* p0 = base + (size_t)i0 * DM;
        const float* p1 = base + (size_t)i1 * DM;
        float4 x0a = *(const float4*)p0, x0b = *(const float4*)(p0 + 4);
        float4 x1a = *(const float4*)p1, x1b = *(const float4*)(p1 + 4);
        acc[0] += w0*x0a.x + w1*x1a.x; acc[1] += w0*x0a.y + w1*x1a.y;
        acc[2] += w0*x0a.z + w1*x1a.z; acc[3] += w0*x0a.w + w1*x1a.w;
        acc[4] += w0*x0b.x + w1*x1b.x; acc[5] += w0*x0b.y + w1*x1b.y;
        acc[6] += w0*x0b.z + w1*x1b.z; acc[7] += w0*x0b.w + w1*x1b.w;
    }
    float scale = 1.0f / fmaxf((float)(hi - lo + 1), 1e-8f);
#pragma unroll
    for (int i = 0; i < 8; i++) acc[i] *= scale;

    float* ao = Actx + (size_t)row * DM + lane * 8;
    *(float4*)ao       = *(float4*)&acc[0];
    *(float4*)(ao + 4) = *(float4*)&acc[4];

    float q = 0.f;
#pragma unroll
    for (int i = 0; i < 8; i++) q += acc[i] * acc[i];
    q = warp_sum(q);
    float ra = 1.0f / fmaxf(sqrtf(q), 1e-8f);
    float rv = rnv[row];

    const float* vr = V + (size_t)row * DM + lane * 8;
    float v[8];
    *(float4*)&v[0] = *(const float4*)vr;
    *(float4*)&v[4] = *(const float4*)(vr + 4);

    __half an[8], vn[8], pr[8];
#pragma unroll
    for (int i = 0; i < 8; i++) {
        float anf = acc[i] * ra, vnf = v[i] * rv;
        an[i] = __float2half(anf);
        vn[i] = __float2half(vnf);
        pr[i] = __float2half(anf * vnf);
    }
    size_t xb = (size_t)row * XDIM + lane * 8;
    *(uint4*)&XH[xb]        = *(uint4*)an;
    *(uint4*)&XH[xb + DM]   = *(uint4*)vn;
    *(uint4*)&XH[xb + 2*DM] = *(uint4*)pr;
}

// ---------------- final: gate from logits, blend (warp per row) ----------------
__global__ void __launch_bounds__(256) final_kernel(
    const float* __restrict__ logits, const float* __restrict__ Actx,
    const float* __restrict__ V, const float* __restrict__ b2,
    float* __restrict__ Out)
{
    int row  = blockIdx.x * 8 + (threadIdx.x >> 5);
    int lane = threadIdx.x & 31;

    float logit = fminf(fmaxf(logits[row] + b2[0], -12.0f), 12.0f);
    float g = 1.0f / (1.0f + expf(-logit));
    g = fminf(fmaxf(g, 0.05f), 0.95f);
    float om = 1.0f - g;

    const float4* av = (const float4*)(Actx + (size_t)row * DM);
    const float4* vv = (const float4*)(V    + (size_t)row * DM);
    float4*       ov = (float4*)(Out + (size_t)row * DM);
#pragma unroll
    for (int j = 0; j < 2; j++) {
        int d4 = lane * 2 + j;
        float4 a = av[d4], v = vv[d4];
        ov[d4] = make_float4(g*a.x + om*v.x, g*a.y + om*v.y,
                             g*a.z + om*v.z, g*a.w + om*v.w);
    }
}

// ---------------- launch ----------------
extern "C" void kernel_launch(void* const* d_in, const int* in_sizes, int n_in,
                              void* d_out, int out_size)
{
    const float* video = (const float*)d_in[0];
    const float* audio = (const float*)d_in[1];
    const float* Wv    = (const float*)d_in[2];
    const float* bv    = (const float*)d_in[3];
    const float* Wa    = (const float*)d_in[4];
    const float* ba    = (const float*)d_in[5];
    const float* theta = (const float*)d_in[6];
    const float* W1    = (const float*)d_in[7];
    const float* b1    = (const float*)d_in[8];
    const float* W2    = (const float*)d_in[9];
    const float* b2    = (const float*)d_in[10];
    float* out = (float*)d_out;

    float *pv, *pa, *pactx, *prnv, *plog;
    __half *pvf, *paf, *pxf, *pwv, *pwa, *pw1;
    cudaGetSymbolAddress((void**)&pv,    g_v);
    cudaGetSymbolAddress((void**)&pa,    g_a);
    cudaGetSymbolAddress((void**)&pactx, g_actx);
    cudaGetSymbolAddress((void**)&prnv,  g_rnv);
    cudaGetSymbolAddress((void**)&plog,  g_logits);
    cudaGetSymbolAddress((void**)&pvf,   g_vf);
    cudaGetSymbolAddress((void**)&paf,   g_af);
    cudaGetSymbolAddress((void**)&pxf,   g_xf);
    cudaGetSymbolAddress((void**)&pwv,   g_wv);
    cudaGetSymbolAddress((void**)&pwa,   g_wa);
    cudaGetSymbolAddress((void**)&pw1,   g_w1);

    cudaFuncSetAttribute(tc_gemm_ln,       cudaFuncAttributeMaxDynamicSharedMemorySize, SMEM_LN);
    cudaFuncSetAttribute(tc_gemm_gelu_dot, cudaFuncAttributeMaxDynamicSharedMemorySize, SMEM_GELU);

    cvt_kernel<<<(MROWS*VDIM/4 + 255)/256, 256>>>(video, pvf, MROWS*VDIM/4);             // 1
    wcvt_kernel<<<(VDIM*DM + 255)/256, 256>>>(Wv, pwv, VDIM, DM);                        // 2
    wcvt_kernel<<<(ADIM*DM + 255)/256, 256>>>(Wa, pwa, ADIM, DM);                        // 3
    tc_gemm_ln<<<MROWS/128, 512, SMEM_LN>>>(pvf, pwv, bv, pv, prnv, VDIM);               // 4
    cvt_kernel<<<(MROWS*ADIM/4 + 255)/256, 256>>>(audio, paf, MROWS*ADIM/4);             // 5
    tc_gemm_ln<<<MROWS/128, 512, SMEM_LN>>>(paf, pwa, ba, pa, (float*)nullptr, ADIM);    // 6
    wcvt_kernel<<<(XDIM*HID + 255)/256, 256>>>(W1, pw1, XDIM, HID);                      // 7
    zero_kernel<<<MROWS/256, 256>>>(plog, MROWS);                                        // 8
    shiftbuildx_kernel<<<MROWS/8, 256>>>(pa, pv, prnv, pactx, pxf, theta);               // 9
    tc_gemm_gelu_dot<<<dim3(HID/128, MROWS/128), 256, SMEM_GELU>>>(                      // 10
        pxf, pw1, b1, W2, plog, XDIM);
    final_kernel<<<MROWS/8, 256>>>(plog, pactx, pv, b2, out);                            // 11
}